// round 10
// baseline (speedup 1.0000x reference)
#include <cuda_runtime.h>
#include <cuda_fp16.h>
#include <cstddef>
#include <cstdint>

// ---------------------------------------------------------------------------
// Problem constants
// ---------------------------------------------------------------------------
#define B     4
#define N1    2048
#define N2    2048
#define D     1024
#define HEADS 8
#define DHEAD 64
#define INNER (HEADS * DHEAD)     // 512
#define NKV   (N1 + N2)           // 4096
#define MTOT  (B * N1)            // 8192

#define SCALE_Q 0.18033688011112042f   // 0.125 * log2(e)

// Scratch (device globals — no allocation allowed), all fp16
__device__ __half g_q1[(size_t)B * N1 * INNER];
__device__ __half g_k [(size_t)B * NKV * INNER];
__device__ __half g_v [(size_t)B * NKV * INNER];
__device__ __half g_ao[(size_t)B * N1 * INNER];
#define WSZ (1024 * 512)
__device__ __half g_wt[6 * WSZ];                  // transposed weights [N,K]
__device__ __half g_xr[2 * (size_t)MTOT * D];     // converted x1,x2

// ---------------------------------------------------------------------------
// PTX helpers (baseline sm_80-level only — safe for compute_103 target)
// ---------------------------------------------------------------------------
__device__ __forceinline__ uint32_t smem_u32(const void* p) {
    uint32_t a;
    asm("{ .reg .u64 t; cvta.to.shared.u64 t, %1; cvt.u32.u64 %0, t; }"
        : "=r"(a) : "l"(p));
    return a;
}
__device__ __forceinline__ void cpasync16(uint32_t dst, const void* src) {
    asm volatile("cp.async.cg.shared.global [%0], [%1], 16;"
                 :: "r"(dst), "l"(src) : "memory");
}
#define CP_COMMIT() asm volatile("cp.async.commit_group;" ::: "memory")
#define CP_WAIT0()  asm volatile("cp.async.wait_group 0;" ::: "memory")
#define CP_WAIT1()  asm volatile("cp.async.wait_group 1;" ::: "memory")

// f16 mma m16n8k16, f32 accumulate. A row-major (16x16), B col-major (16x8).
__device__ __forceinline__ void mma_f16(float* d, const uint32_t* a, const uint32_t* b) {
    asm volatile(
        "mma.sync.aligned.m16n8k16.row.col.f32.f16.f16.f32 "
        "{%0,%1,%2,%3}, {%4,%5,%6,%7}, {%8,%9}, {%0,%1,%2,%3};"
        : "+f"(d[0]), "+f"(d[1]), "+f"(d[2]), "+f"(d[3])
        : "r"(a[0]), "r"(a[1]), "r"(a[2]), "r"(a[3]), "r"(b[0]), "r"(b[1]));
}

__device__ __forceinline__ void ldmatrix_x4(
    uint32_t& r0, uint32_t& r1, uint32_t& r2, uint32_t& r3, uint32_t addr)
{
    asm volatile("ldmatrix.sync.aligned.m8n8.x4.shared.b16 {%0,%1,%2,%3}, [%4];"
                 : "=r"(r0), "=r"(r1), "=r"(r2), "=r"(r3) : "r"(addr));
}
__device__ __forceinline__ void ldmatrix_x4_trans(
    uint32_t& r0, uint32_t& r1, uint32_t& r2, uint32_t& r3, uint32_t addr)
{
    asm volatile("ldmatrix.sync.aligned.m8n8.x4.trans.shared.b16 {%0,%1,%2,%3}, [%4];"
                 : "=r"(r0), "=r"(r1), "=r"(r2), "=r"(r3) : "r"(addr));
}

__device__ __forceinline__ uint32_t packh2(float x, float y) {
    __half2 h = __floats2half2_rn(x, y);
    return *reinterpret_cast<uint32_t*>(&h);
}
__device__ __forceinline__ uint32_t ldh2(const __half* p) {
    return *reinterpret_cast<const uint32_t*>(p);
}

// ---------------------------------------------------------------------------
// Fused weight transpose + f16 convert: 6 weights -> g_wt (each [N,K])
// ---------------------------------------------------------------------------
__global__ void transpose6(const float* __restrict__ Wq1, const float* __restrict__ Wk1,
                           const float* __restrict__ Wv1, const float* __restrict__ Wk2,
                           const float* __restrict__ Wv2, const float* __restrict__ Wo,
                           __half* __restrict__ wt)
{
    __shared__ float t[32][33];
    const int z = blockIdx.z;
    const float* src = (z == 0) ? Wq1 : (z == 1) ? Wk1 : (z == 2) ? Wv1
                     : (z == 3) ? Wk2 : (z == 4) ? Wv2 : Wo;
    const int R = (z < 5) ? D : INNER;
    const int C = (z < 5) ? INNER : D;
    __half* dst = wt + (size_t)z * WSZ;

    const int bx = blockIdx.x * 32, by = blockIdx.y * 32;
    if (bx >= C || by >= R) return;
    const int x = bx + threadIdx.x;
    for (int i = threadIdx.y; i < 32; i += 8)
        t[i][threadIdx.x] = src[(size_t)(by + i) * C + x];
    __syncthreads();
    const int ox = by + threadIdx.x;
    for (int i = threadIdx.y; i < 32; i += 8)
        dst[(size_t)(bx + i) * R + ox] = __float2half_rn(t[threadIdx.x][i]);
}

// ---------------------------------------------------------------------------
// Convert x1, x2 to f16 into g_xr
// ---------------------------------------------------------------------------
#define XF4 ((size_t)MTOT * D / 4)
__global__ void conv_x(const float* __restrict__ x1, const float* __restrict__ x2,
                       __half* __restrict__ xr)
{
    const size_t total = 2 * XF4;
    for (size_t i = (size_t)blockIdx.x * blockDim.x + threadIdx.x;
         i < total; i += (size_t)gridDim.x * blockDim.x) {
        const float4 v = (i < XF4) ? ((const float4*)x1)[i] : ((const float4*)x2)[i - XF4];
        uint2 o;
        o.x = packh2(v.x, v.y);
        o.y = packh2(v.z, v.w);
        ((uint2*)xr)[i] = o;
    }
}

// ---------------------------------------------------------------------------
// cp.async 3-stage f16 GEMM core (128x128 tile, BK=64, 8 warps).
// Fragments via ldmatrix.x4.  Smem pitch 72 halves (144B: conflict-free).
// Stage = A(128x72) + B(128x72) halves = 36864 B; 3 stages = 110592 B.
// ---------------------------------------------------------------------------
#define KP 72
#define GBUF (128 * KP)                 // halves per matrix buffer (9216)
#define GSTG (2 * GBUF)                 // halves per stage

__device__ __forceinline__ void gemm_core(
    const __half* __restrict__ A, const __half* __restrict__ Bt,
    void* __restrict__ C, const float* __restrict__ bias,
    int K, int N, size_t cstride, size_t coff, float scale, bool outHalf)
{
    extern __shared__ __half gsm[];

    const int tid = threadIdx.x;
    const int w = tid >> 5, lane = tid & 31;
    const int g = lane >> 2, tg = lane & 3;
    const int wm = (w & 1) * 64, wn = (w >> 1) * 32;
    const int m0 = blockIdx.y * 128, n0 = blockIdx.x * 128;

    // cp.async mapping: row lr (0..127), half-offset lc in {0,32}, 4x16B chunks
    const int lr = tid >> 1;
    const int lc = (tid & 1) * 32;

    const __half* Ag = A  + (size_t)(m0 + lr) * K + lc;
    const __half* Bg = Bt + (size_t)(n0 + lr) * K + lc;

    const uint32_t smb  = smem_u32(gsm);
    const uint32_t rowA = (uint32_t)(lr * KP + lc) * 2;    // byte off in stage
    const uint32_t rowB = rowA + GBUF * 2;

    // ldmatrix lane roles
    const int sub = lane >> 3, rw = lane & 7;
    const int a_roff = (sub & 1) * 8, a_koff = (sub >> 1) * 8;
    const int b_roff = (sub >> 1) * 8, b_koff = (sub & 1) * 8;

    const int S = K >> 6;     // BK=64 rounds (>=8 always)

    // preload stages 0,1
    #pragma unroll
    for (int s = 0; s < 2; s++) {
        const uint32_t sb = smb + (uint32_t)s * (GSTG * 2);
        #pragma unroll
        for (int c = 0; c < 4; c++) {
            cpasync16(sb + rowA + 16 * c, Ag + (size_t)s * 64 + 8 * c);
            cpasync16(sb + rowB + 16 * c, Bg + (size_t)s * 64 + 8 * c);
        }
        CP_COMMIT();
    }

    float acc[4][4][4] = {};
    int st = 0, pst = 2;
    for (int s = 0; s < S; s++) {
        if (s + 1 < S) { CP_WAIT1(); } else { CP_WAIT0(); }
        __syncthreads();
        if (s + 2 < S) {
            const uint32_t sb = smb + (uint32_t)pst * (GSTG * 2);
            const __half* Ag2 = Ag + (size_t)(s + 2) * 64;
            const __half* Bg2 = Bg + (size_t)(s + 2) * 64;
            #pragma unroll
            for (int c = 0; c < 4; c++) {
                cpasync16(sb + rowA + 16 * c, Ag2 + 8 * c);
                cpasync16(sb + rowB + 16 * c, Bg2 + 8 * c);
            }
            CP_COMMIT();
        }
        const uint32_t asb = smb + (uint32_t)st * (GSTG * 2);
        const uint32_t bsb = asb + GBUF * 2;

        #pragma unroll
        for (int ks = 0; ks < 4; ks++) {          // four k16 slices (BK=64)
            const int k0 = 16 * ks;
            uint32_t af[4][4], bf[4][2];
            #pragma unroll
            for (int mt = 0; mt < 4; mt++) {
                const uint32_t aa = asb +
                    (uint32_t)((wm + 16 * mt + a_roff + rw) * KP + k0 + a_koff) * 2;
                ldmatrix_x4(af[mt][0], af[mt][1], af[mt][2], af[mt][3], aa);
            }
            #pragma unroll
            for (int np = 0; np < 2; np++) {
                const uint32_t ba = bsb +
                    (uint32_t)((wn + 16 * np + b_roff + rw) * KP + k0 + b_koff) * 2;
                ldmatrix_x4(bf[2 * np][0], bf[2 * np][1],
                            bf[2 * np + 1][0], bf[2 * np + 1][1], ba);
            }
            #pragma unroll
            for (int mt = 0; mt < 4; mt++)
                #pragma unroll
                for (int nt = 0; nt < 4; nt++)
                    mma_f16(acc[mt][nt], af[mt], bf[nt]);
        }
        st  = (st  == 2) ? 0 : st + 1;
        pst = (pst == 2) ? 0 : pst + 1;
    }

    #pragma unroll
    for (int mt = 0; mt < 4; mt++) {
        const size_t r0 = (size_t)(m0 + wm + 16 * mt + g);
        const size_t r1 = r0 + 8;
        const size_t o0 = (r0 >> 11) * cstride + (r0 & 2047) * N + coff;
        const size_t o1 = (r1 >> 11) * cstride + (r1 & 2047) * N + coff;
        #pragma unroll
        for (int nt = 0; nt < 4; nt++) {
            const int cc = n0 + wn + 8 * nt + 2 * tg;
            float v00 = acc[mt][nt][0] * scale;
            float v01 = acc[mt][nt][1] * scale;
            float v10 = acc[mt][nt][2] * scale;
            float v11 = acc[mt][nt][3] * scale;
            if (outHalf) {
                *(uint32_t*)((__half*)C + o0 + cc) = packh2(v00, v01);
                *(uint32_t*)((__half*)C + o1 + cc) = packh2(v10, v11);
            } else {
                const float bx = bias ? bias[cc] : 0.f;
                const float by = bias ? bias[cc + 1] : 0.f;
                *(float2*)((float*)C + o0 + cc) = make_float2(v00 + bx, v01 + by);
                *(float2*)((float*)C + o1 + cc) = make_float2(v10 + bx, v11 + by);
            }
        }
    }
}

__global__ __launch_bounds__(256, 2)
void gemm5(const __half* __restrict__ x1r, const __half* __restrict__ x2r,
           const __half* __restrict__ wt,
           __half* __restrict__ q1, __half* __restrict__ k, __half* __restrict__ v)
{
    const int z = blockIdx.z;
    const __half* A = (z < 3) ? x1r : x2r;
    const __half* W = wt + (size_t)z * WSZ;
    const size_t kvs  = (size_t)NKV * INNER;
    const size_t off2 = (size_t)N1 * INNER;
    __half* Cp; size_t cs, co; float sc;
    if (z == 0)      { Cp = q1; cs = (size_t)N1 * INNER; co = 0;    sc = SCALE_Q; }
    else if (z == 1) { Cp = k;  cs = kvs;                co = 0;    sc = 1.f; }
    else if (z == 2) { Cp = v;  cs = kvs;                co = 0;    sc = 1.f; }
    else if (z == 3) { Cp = k;  cs = kvs;                co = off2; sc = 1.f; }
    else             { Cp = v;  cs = kvs;                co = off2; sc = 1.f; }
    gemm_core(A, W, Cp, nullptr, D, INNER, cs, co, sc, true);
}

__global__ __launch_bounds__(256, 2)
void gemmO(const __half* __restrict__ ao, const __half* __restrict__ wt5,
           float* __restrict__ out, const float* __restrict__ bo)
{
    gemm_core(ao, wt5, out, bo, INNER, D, (size_t)N1 * D, 0, 1.f, false);
}

// ---------------------------------------------------------------------------
// Flash attention v6: all-f16 MMA, ldmatrix fragments, 3-stage KV ring.
// Block 256 thr (8 warps), q-tile 128 (warp w: rows 16w..16w+16), kv-tile 64.
// Stage = K(64x72)+V(64x72) halves = 18432 B; 3 stages = 55296 B.
// ---------------------------------------------------------------------------
#define APH 72
#define KV_H   (64 * APH)           // halves per K (or V) tile (4608)
#define FSTG_H (2 * KV_H)           // halves per stage

__global__ __launch_bounds__(256, 2)
void flash6(const __half* __restrict__ q, const __half* __restrict__ kc,
            const __half* __restrict__ vc, __half* __restrict__ ao)
{
    extern __shared__ __half fsm[];

    const int b  = blockIdx.z;
    const int h  = blockIdx.y;
    const int qt = blockIdx.x;
    const int tid  = threadIdx.x;
    const int w = tid >> 5, lane = tid & 31;
    const int g = lane >> 2, tg = lane & 3;
    const int m0 = 16 * w;

    const __half* qb = q  + ((size_t)b * N1 + (size_t)qt * 128) * INNER + h * DHEAD;
    const __half* kb = kc + (size_t)b * NKV * INNER + h * DHEAD;
    const __half* vb = vc + (size_t)b * NKV * INNER + h * DHEAD;

    const uint32_t smb = smem_u32(fsm);

    const int cr = tid >> 2;
    const int cc0 = (tid & 3) * 16;
    const uint32_t rowK = (uint32_t)(cr * APH + cc0) * 2;   // byte off in stage
    const uint32_t rowV = rowK + KV_H * 2;

    const int NT = NKV / 64;

    // --- preload KV tiles 0 and 1 ---
    #pragma unroll
    for (int s = 0; s < 2; s++) {
        const uint32_t sb = smb + (uint32_t)s * (FSTG_H * 2);
        const __half* ks = kb + (size_t)s * 64 * INNER + (size_t)cr * INNER + cc0;
        const __half* vs = vb + (size_t)s * 64 * INNER + (size_t)cr * INNER + cc0;
        #pragma unroll
        for (int c = 0; c < 2; c++) {
            cpasync16(sb + rowK + 16 * c, ks + 8 * c);
            cpasync16(sb + rowV + 16 * c, vs + 8 * c);
        }
        CP_COMMIT();
    }

    // --- Q A-fragments from gmem (16 regs: 4 k-slices x 4) ---
    uint32_t qaf[4][4];
    {
        const __half* q0 = qb + (size_t)(m0 + g) * INNER;
        const __half* q1r = q0 + 8 * INNER;
        #pragma unroll
        for (int s = 0; s < 4; s++) {
            qaf[s][0] = ldh2(q0  + 16 * s + 2 * tg);
            qaf[s][1] = ldh2(q1r + 16 * s + 2 * tg);
            qaf[s][2] = ldh2(q0  + 16 * s + 2 * tg + 8);
            qaf[s][3] = ldh2(q1r + 16 * s + 2 * tg + 8);
        }
    }

    float accO[8][4] = {};
    float mrun0 = -1e30f, mrun1 = -1e30f, lrun0 = 0.f, lrun1 = 0.f;

    // ldmatrix lane roles
    const int sub = lane >> 3, rw = lane & 7;
    const int k_roff = (sub >> 1) * 8, k_koff = (sub & 1) * 8;
    const int vr = (sub & 1) * 8 + rw;
    const int vcb = (sub >> 1) * 8;

    int st = 0, pst = 2;
    for (int j = 0; j < NT; j++) {
        if (j + 1 < NT) { CP_WAIT1(); } else { CP_WAIT0(); }
        __syncthreads();

        if (j + 2 < NT) {
            const uint32_t sb = smb + (uint32_t)pst * (FSTG_H * 2);
            const __half* ks = kb + (size_t)(j + 2) * 64 * INNER + (size_t)cr * INNER + cc0;
            const __half* vs = vb + (size_t)(j + 2) * 64 * INNER + (size_t)cr * INNER + cc0;
            #pragma unroll
            for (int c = 0; c < 2; c++) {
                cpasync16(sb + rowK + 16 * c, ks + 8 * c);
                cpasync16(sb + rowV + 16 * c, vs + 8 * c);
            }
            CP_COMMIT();
        }

        const uint32_t ksb = smb + (uint32_t)st * (FSTG_H * 2);
        const uint32_t vsb = ksb + KV_H * 2;

        // --- S = Q @ K^T (warp: 16x64): ldmatrix.x4 B-frags, 32 f16 MMAs ---
        float sacc[8][4] = {};
        #pragma unroll
        for (int ks = 0; ks < 4; ks++) {
            const int k0 = 16 * ks;
            #pragma unroll
            for (int np = 0; np < 4; np++) {
                uint32_t b0, b1, b2, b3;
                const uint32_t ka = ksb +
                    (uint32_t)((16 * np + k_roff + rw) * APH + k0 + k_koff) * 2;
                ldmatrix_x4(b0, b1, b2, b3, ka);
                uint32_t bf0[2] = { b0, b1 };
                uint32_t bf1[2] = { b2, b3 };
                mma_f16(sacc[2 * np],     qaf[ks], bf0);
                mma_f16(sacc[2 * np + 1], qaf[ks], bf1);
            }
        }

        // --- register online softmax ---
        float rm0 = -1e30f, rm1 = -1e30f;
        #pragma unroll
        for (int nt = 0; nt < 8; nt++) {
            rm0 = fmaxf(rm0, fmaxf(sacc[nt][0], sacc[nt][1]));
            rm1 = fmaxf(rm1, fmaxf(sacc[nt][2], sacc[nt][3]));
        }
        #pragma unroll
        for (int off = 1; off <= 2; off <<= 1) {
            rm0 = fmaxf(rm0, __shfl_xor_sync(0xFFFFFFFFu, rm0, off));
            rm1 = fmaxf(rm1, __shfl_xor_sync(0xFFFFFFFFu, rm1, off));
        }
        const float mn0 = fmaxf(mrun0, rm0);
        const float mn1 = fmaxf(mrun1, rm1);
        const float al0 = exp2f(mrun0 - mn0);
        const float al1 = exp2f(mrun1 - mn1);

        float rs0 = 0.f, rs1 = 0.f;
        uint32_t paf[4][4];                  // P A-frags, packed while exping
        #pragma unroll
        for (int ks = 0; ks < 4; ks++) {
            const int e0 = 2 * ks, e1 = 2 * ks + 1;
            float p00 = exp2f(sacc[e0][0] - mn0);
            float p01 = exp2f(sacc[e0][1] - mn0);
            float p10 = exp2f(sacc[e0][2] - mn1);
            float p11 = exp2f(sacc[e0][3] - mn1);
            float p20 = exp2f(sacc[e1][0] - mn0);
            float p21 = exp2f(sacc[e1][1] - mn0);
            float p30 = exp2f(sacc[e1][2] - mn1);
            float p31 = exp2f(sacc[e1][3] - mn1);
            rs0 += p00 + p01 + p20 + p21;
            rs1 += p10 + p11 + p30 + p31;
            paf[ks][0] = packh2(p00, p01);
            paf[ks][1] = packh2(p10, p11);
            paf[ks][2] = packh2(p20, p21);
            paf[ks][3] = packh2(p30, p31);
        }
        #pragma unroll
        for (int off = 1; off <= 2; off <<= 1) {
            rs0 += __shfl_xor_sync(0xFFFFFFFFu, rs0, off);
            rs1 += __shfl_xor_sync(0xFFFFFFFFu, rs1, off);
        }
        lrun0 = lrun0 * al0 + rs0;
        lrun1 = lrun1 * al1 + rs1;
        mrun0 = mn0;
        mrun1 = mn1;

        // rescale O only if some row max changed anywhere in the warp
        if (!__all_sync(0xFFFFFFFFu, (al0 == 1.f) && (al1 == 1.f))) {
            #pragma unroll
            for (int nt = 0; nt < 8; nt++) {
                accO[nt][0] *= al0; accO[nt][1] *= al0;
                accO[nt][2] *= al1; accO[nt][3] *= al1;
            }
        }

        // --- O += P @ V : ldmatrix.x4.trans B-frags, 32 f16 MMAs ---
        #pragma unroll
        for (int ks = 0; ks < 4; ks++) {
            #pragma unroll
            for (int dp = 0; dp < 4; dp++) {
                uint32_t r0, r1, r2, r3;
                const uint32_t addr = vsb +
                    (uint32_t)((16 * ks + vr) * APH + 16 * dp + vcb) * 2;
                ldmatrix_x4_trans(r0, r1, r2, r3, addr);
                uint32_t bf0[2] = { r0, r1 };
                uint32_t bf1[2] = { r2, r3 };
                mma_f16(accO[2 * dp],     paf[ks], bf0);
                mma_f16(accO[2 * dp + 1], paf[ks], bf1);
            }
        }

        st  = (st  == 2) ? 0 : st + 1;
        pst = (pst == 2) ? 0 : pst + 1;
    }

    // --- normalize + write f16 ---
    {
        const float li0 = 1.0f / lrun0;
        const float li1 = 1.0f / lrun1;
        const size_t r = (size_t)b * N1 + (size_t)qt * 128 + m0 + g;
        __half* d0 = ao + r * INNER + h * DHEAD;
        __half* d1 = d0 + 8 * INNER;
        #pragma unroll
        for (int nt = 0; nt < 8; nt++) {
            const int cc = 8 * nt + 2 * tg;
            *(uint32_t*)(d0 + cc) = packh2(accO[nt][0] * li0, accO[nt][1] * li0);
            *(uint32_t*)(d1 + cc) = packh2(accO[nt][2] * li1, accO[nt][3] * li1);
        }
    }
}

// ---------------------------------------------------------------------------
// Launch
// ---------------------------------------------------------------------------
extern "C" void kernel_launch(void* const* d_in, const int* in_sizes, int n_in,
                              void* d_out, int out_size)
{
    (void)in_sizes; (void)n_in; (void)out_size;

    const float* x1  = (const float*)d_in[0];
    const float* x2  = (const float*)d_in[1];
    const float* Wq1 = (const float*)d_in[2];
    const float* Wk1 = (const float*)d_in[3];
    const float* Wv1 = (const float*)d_in[4];
    const float* Wk2 = (const float*)d_in[5];
    const float* Wv2 = (const float*)d_in[6];
    const float* Wo  = (const float*)d_in[7];
    const float* bo  = (const float*)d_in[8];
    float* out = (float*)d_out;

    __half *q1, *kbuf, *vbuf, *aobuf, *wt, *xr;
    cudaGetSymbolAddress((void**)&q1,    g_q1);
    cudaGetSymbolAddress((void**)&kbuf,  g_k);
    cudaGetSymbolAddress((void**)&vbuf,  g_v);
    cudaGetSymbolAddress((void**)&aobuf, g_ao);
    cudaGetSymbolAddress((void**)&wt,    g_wt);
    cudaGetSymbolAddress((void**)&xr,    g_xr);

    const int gemm_smem  = 3 * GSTG   * (int)sizeof(__half);   // 110592 B
    const int flash_smem = 3 * FSTG_H * (int)sizeof(__half);   // 55296 B
    cudaFuncSetAttribute(gemm5,  cudaFuncAttributeMaxDynamicSharedMemorySize, gemm_smem);
    cudaFuncSetAttribute(gemmO,  cudaFuncAttributeMaxDynamicSharedMemorySize, gemm_smem);
    cudaFuncSetAttribute(flash6, cudaFuncAttributeMaxDynamicSharedMemorySize, flash_smem);

    transpose6<<<dim3(32, 32, 6), dim3(32, 8)>>>(Wq1, Wk1, Wv1, Wk2, Wv2, Wo, wt);
    conv_x<<<4096, 256>>>(x1, x2, xr);

    gemm5<<<dim3(INNER / 128, MTOT / 128, 5), 256, gemm_smem>>>(
        xr, xr + (size_t)MTOT * D, wt, q1, kbuf, vbuf);

    flash6<<<dim3(N1 / 128, HEADS, B), 256, flash_smem>>>(q1, kbuf, vbuf, aobuf);

    gemmO<<<dim3(D / 128, MTOT / 128, 1), 256, gemm_smem>>>(aobuf, wt + 5 * WSZ, out, bo);
}

// round 11
// speedup vs baseline: 1.0852x; 1.0852x over previous
#include <cuda_runtime.h>
#include <cuda_fp16.h>
#include <cstddef>
#include <cstdint>

// ---------------------------------------------------------------------------
// Problem constants
// ---------------------------------------------------------------------------
#define B     4
#define N1    2048
#define N2    2048
#define D     1024
#define HEADS 8
#define DHEAD 64
#define INNER (HEADS * DHEAD)     // 512
#define NKV   (N1 + N2)           // 4096
#define MTOT  (B * N1)            // 8192
#define NSPLIT 4
#define KVS   (NKV / NSPLIT)      // 1024 keys per split

#define SCALE_Q 0.18033688011112042f   // 0.125 * log2(e)

// Scratch (device globals — no allocation allowed), all fp16
__device__ __half g_q1[(size_t)B * N1 * INNER];
__device__ __half g_k [(size_t)B * NKV * INNER];
__device__ __half g_v [(size_t)B * NKV * INNER];
__device__ __half g_ao[(size_t)B * N1 * INNER];
#define WSZ (1024 * 512)
__device__ __half g_wt[6 * WSZ];                  // transposed weights [N,K]
__device__ __half g_xr[2 * (size_t)MTOT * D];     // converted x1,x2
// split-KV partials
#define PBUF ((size_t)B * N1 * INNER)
#define MBUF (B * HEADS * N1)
__device__ __half g_aop[NSPLIT * PBUF];           // unnormalized O partials
__device__ float2 g_ml [NSPLIT * MBUF];           // per-row (m, l), log2 domain

// ---------------------------------------------------------------------------
// PTX helpers (baseline sm_80-level only — safe for compute_103 target)
// ---------------------------------------------------------------------------
__device__ __forceinline__ uint32_t smem_u32(const void* p) {
    uint32_t a;
    asm("{ .reg .u64 t; cvta.to.shared.u64 t, %1; cvt.u32.u64 %0, t; }"
        : "=r"(a) : "l"(p));
    return a;
}
__device__ __forceinline__ void cpasync16(uint32_t dst, const void* src) {
    asm volatile("cp.async.cg.shared.global [%0], [%1], 16;"
                 :: "r"(dst), "l"(src) : "memory");
}
#define CP_COMMIT() asm volatile("cp.async.commit_group;" ::: "memory")
#define CP_WAIT0()  asm volatile("cp.async.wait_group 0;" ::: "memory")

// f16 mma m16n8k16, f32 accumulate. A row-major (16x16), B col-major (16x8).
__device__ __forceinline__ void mma_f16(float* d, const uint32_t* a, const uint32_t* b) {
    asm volatile(
        "mma.sync.aligned.m16n8k16.row.col.f32.f16.f16.f32 "
        "{%0,%1,%2,%3}, {%4,%5,%6,%7}, {%8,%9}, {%0,%1,%2,%3};"
        : "+f"(d[0]), "+f"(d[1]), "+f"(d[2]), "+f"(d[3])
        : "r"(a[0]), "r"(a[1]), "r"(a[2]), "r"(a[3]), "r"(b[0]), "r"(b[1]));
}

__device__ __forceinline__ void ldmatrix_x4(
    uint32_t& r0, uint32_t& r1, uint32_t& r2, uint32_t& r3, uint32_t addr)
{
    asm volatile("ldmatrix.sync.aligned.m8n8.x4.shared.b16 {%0,%1,%2,%3}, [%4];"
                 : "=r"(r0), "=r"(r1), "=r"(r2), "=r"(r3) : "r"(addr));
}
__device__ __forceinline__ void ldmatrix_x4_trans(
    uint32_t& r0, uint32_t& r1, uint32_t& r2, uint32_t& r3, uint32_t addr)
{
    asm volatile("ldmatrix.sync.aligned.m8n8.x4.trans.shared.b16 {%0,%1,%2,%3}, [%4];"
                 : "=r"(r0), "=r"(r1), "=r"(r2), "=r"(r3) : "r"(addr));
}

__device__ __forceinline__ uint32_t packh2(float x, float y) {
    __half2 h = __floats2half2_rn(x, y);
    return *reinterpret_cast<uint32_t*>(&h);
}
__device__ __forceinline__ uint32_t ldh2(const __half* p) {
    return *reinterpret_cast<const uint32_t*>(p);
}

// ---------------------------------------------------------------------------
// Fused weight transpose + f16 convert: 6 weights -> g_wt (each [N,K])
// ---------------------------------------------------------------------------
__global__ void transpose6(const float* __restrict__ Wq1, const float* __restrict__ Wk1,
                           const float* __restrict__ Wv1, const float* __restrict__ Wk2,
                           const float* __restrict__ Wv2, const float* __restrict__ Wo,
                           __half* __restrict__ wt)
{
    __shared__ float t[32][33];
    const int z = blockIdx.z;
    const float* src = (z == 0) ? Wq1 : (z == 1) ? Wk1 : (z == 2) ? Wv1
                     : (z == 3) ? Wk2 : (z == 4) ? Wv2 : Wo;
    const int R = (z < 5) ? D : INNER;
    const int C = (z < 5) ? INNER : D;
    __half* dst = wt + (size_t)z * WSZ;

    const int bx = blockIdx.x * 32, by = blockIdx.y * 32;
    if (bx >= C || by >= R) return;
    const int x = bx + threadIdx.x;
    for (int i = threadIdx.y; i < 32; i += 8)
        t[i][threadIdx.x] = src[(size_t)(by + i) * C + x];
    __syncthreads();
    const int ox = by + threadIdx.x;
    for (int i = threadIdx.y; i < 32; i += 8)
        dst[(size_t)(bx + i) * R + ox] = __float2half_rn(t[threadIdx.x][i]);
}

// ---------------------------------------------------------------------------
// Convert x1, x2 to f16 into g_xr
// ---------------------------------------------------------------------------
#define XF4 ((size_t)MTOT * D / 4)
__global__ void conv_x(const float* __restrict__ x1, const float* __restrict__ x2,
                       __half* __restrict__ xr)
{
    const size_t total = 2 * XF4;
    for (size_t i = (size_t)blockIdx.x * blockDim.x + threadIdx.x;
         i < total; i += (size_t)gridDim.x * blockDim.x) {
        const float4 v = (i < XF4) ? ((const float4*)x1)[i] : ((const float4*)x2)[i - XF4];
        uint2 o;
        o.x = packh2(v.x, v.y);
        o.y = packh2(v.z, v.w);
        ((uint2*)xr)[i] = o;
    }
}

// ---------------------------------------------------------------------------
// cp.async double-buffered f16 GEMM core (128x128, BK=32, 8 warps)  [R9]
// Fragments via ldmatrix.x4.  Smem pitch 40 halves (80B row shift).
// ---------------------------------------------------------------------------
#define KP 40
#define GBUF (128 * KP)                 // halves per matrix buffer

__device__ __forceinline__ void gemm_core(
    const __half* __restrict__ A, const __half* __restrict__ Bt,
    void* __restrict__ C, const float* __restrict__ bias,
    int K, int N, size_t cstride, size_t coff, float scale, bool outHalf)
{
    extern __shared__ __half gsm[];

    const int tid = threadIdx.x;
    const int w = tid >> 5, lane = tid & 31;
    const int g = lane >> 2, tg = lane & 3;
    const int wm = (w & 1) * 64, wn = (w >> 1) * 32;
    const int m0 = blockIdx.y * 128, n0 = blockIdx.x * 128;

    const int lr = tid >> 1;
    const int lc = (tid & 1) * 16;     // halves offset: 0 or 16

    const __half* Ag = A  + (size_t)(m0 + lr) * K + lc;
    const __half* Bg = Bt + (size_t)(n0 + lr) * K + lc;

    const uint32_t smb  = smem_u32(gsm);
    const uint32_t dstA = smb + (uint32_t)(lr * KP + lc) * 2;
    const uint32_t dstB = dstA + GBUF * 2;
    const uint32_t BUFB = 2 * GBUF * 2;

    // ldmatrix lane roles
    const int sub = lane >> 3, rw = lane & 7;
    const int a_roff = (sub & 1) * 8, a_koff = (sub >> 1) * 8;
    const int b_roff = (sub >> 1) * 8, b_koff = (sub & 1) * 8;

    #pragma unroll
    for (int c = 0; c < 2; c++) {
        cpasync16(dstA + 16 * c, Ag + 8 * c);
        cpasync16(dstB + 16 * c, Bg + 8 * c);
    }
    CP_COMMIT();

    float acc[4][4][4] = {};
    const int S = K >> 5;
    for (int s = 0; s < S; s++) {
        CP_WAIT0();
        __syncthreads();
        if (s + 1 < S) {
            const uint32_t off = (uint32_t)((s + 1) & 1) * BUFB;
            const __half* Ag2 = Ag + (s + 1) * 32;
            const __half* Bg2 = Bg + (s + 1) * 32;
            #pragma unroll
            for (int c = 0; c < 2; c++) {
                cpasync16(dstA + off + 16 * c, Ag2 + 8 * c);
                cpasync16(dstB + off + 16 * c, Bg2 + 8 * c);
            }
            CP_COMMIT();
        }
        const uint32_t asb = smb + (uint32_t)((s & 1) * (2 * GBUF)) * 2;
        const uint32_t bsb = asb + GBUF * 2;

        #pragma unroll
        for (int ks = 0; ks < 2; ks++) {          // two k16 slices
            const int k0 = 16 * ks;
            uint32_t af[4][4], bf[4][2];
            #pragma unroll
            for (int mt = 0; mt < 4; mt++) {
                const uint32_t aa = asb +
                    (uint32_t)((wm + 16 * mt + a_roff + rw) * KP + k0 + a_koff) * 2;
                ldmatrix_x4(af[mt][0], af[mt][1], af[mt][2], af[mt][3], aa);
            }
            #pragma unroll
            for (int np = 0; np < 2; np++) {
                const uint32_t ba = bsb +
                    (uint32_t)((wn + 16 * np + b_roff + rw) * KP + k0 + b_koff) * 2;
                ldmatrix_x4(bf[2 * np][0], bf[2 * np][1],
                            bf[2 * np + 1][0], bf[2 * np + 1][1], ba);
            }
            #pragma unroll
            for (int mt = 0; mt < 4; mt++)
                #pragma unroll
                for (int nt = 0; nt < 4; nt++)
                    mma_f16(acc[mt][nt], af[mt], bf[nt]);
        }
    }

    #pragma unroll
    for (int mt = 0; mt < 4; mt++) {
        const size_t r0 = (size_t)(m0 + wm + 16 * mt + g);
        const size_t r1 = r0 + 8;
        const size_t o0 = (r0 >> 11) * cstride + (r0 & 2047) * N + coff;
        const size_t o1 = (r1 >> 11) * cstride + (r1 & 2047) * N + coff;
        #pragma unroll
        for (int nt = 0; nt < 4; nt++) {
            const int cc = n0 + wn + 8 * nt + 2 * tg;
            float v00 = acc[mt][nt][0] * scale;
            float v01 = acc[mt][nt][1] * scale;
            float v10 = acc[mt][nt][2] * scale;
            float v11 = acc[mt][nt][3] * scale;
            if (outHalf) {
                *(uint32_t*)((__half*)C + o0 + cc) = packh2(v00, v01);
                *(uint32_t*)((__half*)C + o1 + cc) = packh2(v10, v11);
            } else {
                const float bx = bias ? bias[cc] : 0.f;
                const float by = bias ? bias[cc + 1] : 0.f;
                *(float2*)((float*)C + o0 + cc) = make_float2(v00 + bx, v01 + by);
                *(float2*)((float*)C + o1 + cc) = make_float2(v10 + bx, v11 + by);
            }
        }
    }
}

__global__ __launch_bounds__(256, 2)
void gemm5(const __half* __restrict__ x1r, const __half* __restrict__ x2r,
           const __half* __restrict__ wt,
           __half* __restrict__ q1, __half* __restrict__ k, __half* __restrict__ v)
{
    const int z = blockIdx.z;
    const __half* A = (z < 3) ? x1r : x2r;
    const __half* W = wt + (size_t)z * WSZ;
    const size_t kvs  = (size_t)NKV * INNER;
    const size_t off2 = (size_t)N1 * INNER;
    __half* Cp; size_t cs, co; float sc;
    if (z == 0)      { Cp = q1; cs = (size_t)N1 * INNER; co = 0;    sc = SCALE_Q; }
    else if (z == 1) { Cp = k;  cs = kvs;                co = 0;    sc = 1.f; }
    else if (z == 2) { Cp = v;  cs = kvs;                co = 0;    sc = 1.f; }
    else if (z == 3) { Cp = k;  cs = kvs;                co = off2; sc = 1.f; }
    else             { Cp = v;  cs = kvs;                co = off2; sc = 1.f; }
    gemm_core(A, W, Cp, nullptr, D, INNER, cs, co, sc, true);
}

__global__ __launch_bounds__(256, 2)
void gemmO(const __half* __restrict__ ao, const __half* __restrict__ wt5,
           float* __restrict__ out, const float* __restrict__ bo)
{
    gemm_core(ao, wt5, out, bo, INNER, D, (size_t)N1 * D, 0, 1.f, false);
}

// ---------------------------------------------------------------------------
// Flash attention v7: R9 inner loop + split-KV x4.
// blockIdx.z = b*NSPLIT + sp; each CTA handles 1024 keys (NT=16 tiles).
// Writes unnormalized O partial (f16) + per-row (m,l) float2 (log2 domain).
// ---------------------------------------------------------------------------
#define APH 72
#define KV_H   (64 * APH)           // halves per K (or V) tile
#define FBUF_H (2 * KV_H)           // halves per stage (K+V)

__global__ __launch_bounds__(256, 2)
void flash7(const __half* __restrict__ q, const __half* __restrict__ kc,
            const __half* __restrict__ vc,
            __half* __restrict__ aop, float2* __restrict__ ml)
{
    extern __shared__ __half fsm[];

    const int z  = blockIdx.z;
    const int b  = z >> 2;            // NSPLIT == 4
    const int sp = z & 3;
    const int h  = blockIdx.y;
    const int qt = blockIdx.x;
    const int tid  = threadIdx.x;
    const int w = tid >> 5, lane = tid & 31;
    const int g = lane >> 2, tg = lane & 3;
    const int m0 = 16 * w;

    const __half* qb = q  + ((size_t)b * N1 + (size_t)qt * 128) * INNER + h * DHEAD;
    const __half* kb = kc + ((size_t)b * NKV + (size_t)sp * KVS) * INNER + h * DHEAD;
    const __half* vb = vc + ((size_t)b * NKV + (size_t)sp * KVS) * INNER + h * DHEAD;

    const uint32_t smb = smem_u32(fsm);

    const int cr = tid >> 2;
    const int cc0 = (tid & 3) * 16;

    // --- kick off KV tile 0 prefetch ---
    {
        const uint32_t kdst = smb + (uint32_t)(cr * APH + cc0) * 2;
        const uint32_t vdst = kdst + KV_H * 2;
        const __half* ks = kb + (size_t)cr * INNER + cc0;
        const __half* vs = vb + (size_t)cr * INNER + cc0;
        #pragma unroll
        for (int c = 0; c < 2; c++) {
            cpasync16(kdst + 16 * c, ks + 8 * c);
            cpasync16(vdst + 16 * c, vs + 8 * c);
        }
    }
    CP_COMMIT();

    // --- Q A-fragments from gmem (16 regs: 4 k-slices x 4) ---
    uint32_t qaf[4][4];
    {
        const __half* q0 = qb + (size_t)(m0 + g) * INNER;
        const __half* q1r = q0 + 8 * INNER;
        #pragma unroll
        for (int s = 0; s < 4; s++) {
            qaf[s][0] = ldh2(q0  + 16 * s + 2 * tg);
            qaf[s][1] = ldh2(q1r + 16 * s + 2 * tg);
            qaf[s][2] = ldh2(q0  + 16 * s + 2 * tg + 8);
            qaf[s][3] = ldh2(q1r + 16 * s + 2 * tg + 8);
        }
    }

    float accO[8][4] = {};
    float mrun0 = -1e30f, mrun1 = -1e30f, lrun0 = 0.f, lrun1 = 0.f;

    // ldmatrix lane roles
    const int sub = lane >> 3, rw = lane & 7;
    const int k_roff = (sub >> 1) * 8, k_koff = (sub & 1) * 8;
    const int vr = (sub & 1) * 8 + rw;
    const int vcb = (sub >> 1) * 8;

    const int NT = KVS / 64;     // 16
    for (int j = 0; j < NT; j++) {
        CP_WAIT0();
        __syncthreads();

        if (j + 1 < NT) {
            const uint32_t base = smb + (uint32_t)(((j + 1) & 1) * FBUF_H) * 2;
            const uint32_t kdst = base + (uint32_t)(cr * APH + cc0) * 2;
            const uint32_t vdst = kdst + KV_H * 2;
            const __half* ks = kb + (size_t)(j + 1) * 64 * INNER + (size_t)cr * INNER + cc0;
            const __half* vs = vb + (size_t)(j + 1) * 64 * INNER + (size_t)cr * INNER + cc0;
            #pragma unroll
            for (int c = 0; c < 2; c++) {
                cpasync16(kdst + 16 * c, ks + 8 * c);
                cpasync16(vdst + 16 * c, vs + 8 * c);
            }
            CP_COMMIT();
        }

        const uint32_t ksb = smb + (uint32_t)((j & 1) * FBUF_H) * 2;
        const uint32_t vsb = ksb + KV_H * 2;

        // --- S = Q @ K^T (warp: 16x64): ldmatrix.x4 B-frags, 32 f16 MMAs ---
        float sacc[8][4] = {};
        #pragma unroll
        for (int ks = 0; ks < 4; ks++) {
            const int k0 = 16 * ks;
            #pragma unroll
            for (int np = 0; np < 4; np++) {
                uint32_t b0, b1, b2, b3;
                const uint32_t ka = ksb +
                    (uint32_t)((16 * np + k_roff + rw) * APH + k0 + k_koff) * 2;
                ldmatrix_x4(b0, b1, b2, b3, ka);
                uint32_t bf0[2] = { b0, b1 };
                uint32_t bf1[2] = { b2, b3 };
                mma_f16(sacc[2 * np],     qaf[ks], bf0);
                mma_f16(sacc[2 * np + 1], qaf[ks], bf1);
            }
        }

        // --- register online softmax ---
        float rm0 = -1e30f, rm1 = -1e30f;
        #pragma unroll
        for (int nt = 0; nt < 8; nt++) {
            rm0 = fmaxf(rm0, fmaxf(sacc[nt][0], sacc[nt][1]));
            rm1 = fmaxf(rm1, fmaxf(sacc[nt][2], sacc[nt][3]));
        }
        #pragma unroll
        for (int off = 1; off <= 2; off <<= 1) {
            rm0 = fmaxf(rm0, __shfl_xor_sync(0xFFFFFFFFu, rm0, off));
            rm1 = fmaxf(rm1, __shfl_xor_sync(0xFFFFFFFFu, rm1, off));
        }
        const float mn0 = fmaxf(mrun0, rm0);
        const float mn1 = fmaxf(mrun1, rm1);
        const float al0 = exp2f(mrun0 - mn0);
        const float al1 = exp2f(mrun1 - mn1);

        float rs0 = 0.f, rs1 = 0.f;
        uint32_t paf[4][4];                  // P A-frags, packed while exping
        #pragma unroll
        for (int ks = 0; ks < 4; ks++) {
            const int e0 = 2 * ks, e1 = 2 * ks + 1;
            float p00 = exp2f(sacc[e0][0] - mn0);
            float p01 = exp2f(sacc[e0][1] - mn0);
            float p10 = exp2f(sacc[e0][2] - mn1);
            float p11 = exp2f(sacc[e0][3] - mn1);
            float p20 = exp2f(sacc[e1][0] - mn0);
            float p21 = exp2f(sacc[e1][1] - mn0);
            float p30 = exp2f(sacc[e1][2] - mn1);
            float p31 = exp2f(sacc[e1][3] - mn1);
            rs0 += p00 + p01 + p20 + p21;
            rs1 += p10 + p11 + p30 + p31;
            paf[ks][0] = packh2(p00, p01);
            paf[ks][1] = packh2(p10, p11);
            paf[ks][2] = packh2(p20, p21);
            paf[ks][3] = packh2(p30, p31);
        }
        #pragma unroll
        for (int off = 1; off <= 2; off <<= 1) {
            rs0 += __shfl_xor_sync(0xFFFFFFFFu, rs0, off);
            rs1 += __shfl_xor_sync(0xFFFFFFFFu, rs1, off);
        }
        lrun0 = lrun0 * al0 + rs0;
        lrun1 = lrun1 * al1 + rs1;
        mrun0 = mn0;
        mrun1 = mn1;

        // rescale O only if some row max changed anywhere in the warp
        if (!__all_sync(0xFFFFFFFFu, (al0 == 1.f) && (al1 == 1.f))) {
            #pragma unroll
            for (int nt = 0; nt < 8; nt++) {
                accO[nt][0] *= al0; accO[nt][1] *= al0;
                accO[nt][2] *= al1; accO[nt][3] *= al1;
            }
        }

        // --- O += P @ V : ldmatrix.x4.trans B-frags, 32 f16 MMAs ---
        #pragma unroll
        for (int ks = 0; ks < 4; ks++) {
            #pragma unroll
            for (int dp = 0; dp < 4; dp++) {
                uint32_t r0, r1, r2, r3;
                const uint32_t addr = vsb +
                    (uint32_t)((16 * ks + vr) * APH + 16 * dp + vcb) * 2;
                ldmatrix_x4_trans(r0, r1, r2, r3, addr);
                uint32_t bf0[2] = { r0, r1 };
                uint32_t bf1[2] = { r2, r3 };
                mma_f16(accO[2 * dp],     paf[ks], bf0);
                mma_f16(accO[2 * dp + 1], paf[ks], bf1);
            }
        }
    }

    // --- write UNNORMALIZED partial O (f16) + (m,l) per row ---
    {
        const int qr0 = qt * 128 + m0 + g;        // local q row (first strip)
        __half* d0 = aop + (size_t)sp * PBUF
                   + ((size_t)b * N1 + qr0) * INNER + h * DHEAD;
        __half* d1 = d0 + 8 * INNER;
        #pragma unroll
        for (int nt = 0; nt < 8; nt++) {
            const int cc = 8 * nt + 2 * tg;
            *(uint32_t*)(d0 + cc) = packh2(accO[nt][0], accO[nt][1]);
            *(uint32_t*)(d1 + cc) = packh2(accO[nt][2], accO[nt][3]);
        }
        if (tg == 0) {
            float2* mlp = ml + (size_t)sp * MBUF
                        + ((size_t)b * HEADS + h) * N1;
            mlp[qr0]     = make_float2(mrun0, lrun0);
            mlp[qr0 + 8] = make_float2(mrun1, lrun1);
        }
    }
}

// ---------------------------------------------------------------------------
// Combine NSPLIT partials: O = sum_s w_s * O_s / sum_s w_s * l_s,
// w_s = 2^(m_s - m*), m* = max_s m_s.   One block per (b, row).
// Thread t: head h = t>>5, d-pair = (t&31)*2.
// ---------------------------------------------------------------------------
__global__ __launch_bounds__(256)
void combine4(const __half* __restrict__ aop, const float2* __restrict__ ml,
              __half* __restrict__ ao)
{
    const int bid = blockIdx.x;
    const int b   = bid >> 11;           // N1 == 2048
    const int row = bid & 2047;
    const int t   = threadIdx.x;
    const int h   = t >> 5;
    const int d   = (t & 31) * 2;

    const size_t mlIdx = ((size_t)b * HEADS + h) * N1 + row;
    float2 m0 = ml[0 * MBUF + mlIdx];
    float2 m1 = ml[1 * MBUF + mlIdx];
    float2 m2 = ml[2 * MBUF + mlIdx];
    float2 m3 = ml[3 * MBUF + mlIdx];

    const float mm = fmaxf(fmaxf(m0.x, m1.x), fmaxf(m2.x, m3.x));
    const float w0 = exp2f(m0.x - mm);
    const float w1 = exp2f(m1.x - mm);
    const float w2 = exp2f(m2.x - mm);
    const float w3 = exp2f(m3.x - mm);
    const float inv = 1.0f / (w0 * m0.y + w1 * m1.y + w2 * m2.y + w3 * m3.y);

    const size_t ofs = ((size_t)b * N1 + row) * INNER + h * DHEAD + d;
    const __half2 o0 = *(const __half2*)(aop + 0 * PBUF + ofs);
    const __half2 o1 = *(const __half2*)(aop + 1 * PBUF + ofs);
    const __half2 o2 = *(const __half2*)(aop + 2 * PBUF + ofs);
    const __half2 o3 = *(const __half2*)(aop + 3 * PBUF + ofs);

    const float2 f0 = __half22float2(o0);
    const float2 f1 = __half22float2(o1);
    const float2 f2 = __half22float2(o2);
    const float2 f3 = __half22float2(o3);

    const float ox = (w0 * f0.x + w1 * f1.x + w2 * f2.x + w3 * f3.x) * inv;
    const float oy = (w0 * f0.y + w1 * f1.y + w2 * f2.y + w3 * f3.y) * inv;
    *(uint32_t*)(ao + ofs) = packh2(ox, oy);
}

// ---------------------------------------------------------------------------
// Launch
// ---------------------------------------------------------------------------
extern "C" void kernel_launch(void* const* d_in, const int* in_sizes, int n_in,
                              void* d_out, int out_size)
{
    (void)in_sizes; (void)n_in; (void)out_size;

    const float* x1  = (const float*)d_in[0];
    const float* x2  = (const float*)d_in[1];
    const float* Wq1 = (const float*)d_in[2];
    const float* Wk1 = (const float*)d_in[3];
    const float* Wv1 = (const float*)d_in[4];
    const float* Wk2 = (const float*)d_in[5];
    const float* Wv2 = (const float*)d_in[6];
    const float* Wo  = (const float*)d_in[7];
    const float* bo  = (const float*)d_in[8];
    float* out = (float*)d_out;

    __half *q1, *kbuf, *vbuf, *aobuf, *wt, *xr, *aop;
    float2* mlb;
    cudaGetSymbolAddress((void**)&q1,    g_q1);
    cudaGetSymbolAddress((void**)&kbuf,  g_k);
    cudaGetSymbolAddress((void**)&vbuf,  g_v);
    cudaGetSymbolAddress((void**)&aobuf, g_ao);
    cudaGetSymbolAddress((void**)&wt,    g_wt);
    cudaGetSymbolAddress((void**)&xr,    g_xr);
    cudaGetSymbolAddress((void**)&aop,   g_aop);
    cudaGetSymbolAddress((void**)&mlb,   g_ml);

    const int gemm_smem  = 4 * GBUF * (int)sizeof(__half);    // 40960
    const int flash_smem = 2 * FBUF_H * (int)sizeof(__half);  // 36864
    cudaFuncSetAttribute(gemm5,  cudaFuncAttributeMaxDynamicSharedMemorySize, gemm_smem);
    cudaFuncSetAttribute(gemmO,  cudaFuncAttributeMaxDynamicSharedMemorySize, gemm_smem);
    cudaFuncSetAttribute(flash7, cudaFuncAttributeMaxDynamicSharedMemorySize, flash_smem);

    transpose6<<<dim3(32, 32, 6), dim3(32, 8)>>>(Wq1, Wk1, Wv1, Wk2, Wv2, Wo, wt);
    conv_x<<<4096, 256>>>(x1, x2, xr);

    gemm5<<<dim3(INNER / 128, MTOT / 128, 5), 256, gemm_smem>>>(
        xr, xr + (size_t)MTOT * D, wt, q1, kbuf, vbuf);

    flash7<<<dim3(N1 / 128, HEADS, B * NSPLIT), 256, flash_smem>>>(
        q1, kbuf, vbuf, aop, mlb);

    combine4<<<B * N1, 256>>>(aop, mlb, aobuf);

    gemmO<<<dim3(D / 128, MTOT / 128, 1), 256, gemm_smem>>>(aobuf, wt + 5 * WSZ, out, bo);
}

// round 12
// speedup vs baseline: 1.1235x; 1.0352x over previous
#include <cuda_runtime.h>
#include <cuda_fp16.h>
#include <cstddef>
#include <cstdint>

// ---------------------------------------------------------------------------
// Problem constants
// ---------------------------------------------------------------------------
#define B     4
#define N1    2048
#define N2    2048
#define D     1024
#define HEADS 8
#define DHEAD 64
#define INNER (HEADS * DHEAD)     // 512
#define NKV   (N1 + N2)           // 4096
#define MTOT  (B * N1)            // 8192
#define NSPLIT 4
#define KVS   (NKV / NSPLIT)      // 1024 keys per split

#define SCALE_Q 0.18033688011112042f   // 0.125 * log2(e)

// Scratch (device globals — no allocation allowed), all fp16
__device__ __half g_q1[(size_t)B * N1 * INNER];
__device__ __half g_k [(size_t)B * NKV * INNER];
__device__ __half g_v [(size_t)B * NKV * INNER];
__device__ __half g_ao[(size_t)B * N1 * INNER];
#define WSZ (1024 * 512)
__device__ __half g_wt[6 * WSZ];                  // f16 weights, NATIVE [K,N]
__device__ __half g_xr[2 * (size_t)MTOT * D];     // converted x1,x2
// split-KV partials
#define PBUF ((size_t)B * N1 * INNER)
#define MBUF (B * HEADS * N1)
__device__ __half g_aop[NSPLIT * PBUF];           // unnormalized O partials
__device__ float2 g_ml [NSPLIT * MBUF];           // per-row (m, l), log2 domain

// ---------------------------------------------------------------------------
// PTX helpers (baseline sm_80-level only — safe for compute_103 target)
// ---------------------------------------------------------------------------
__device__ __forceinline__ uint32_t smem_u32(const void* p) {
    uint32_t a;
    asm("{ .reg .u64 t; cvta.to.shared.u64 t, %1; cvt.u32.u64 %0, t; }"
        : "=r"(a) : "l"(p));
    return a;
}
__device__ __forceinline__ void cpasync16(uint32_t dst, const void* src) {
    asm volatile("cp.async.cg.shared.global [%0], [%1], 16;"
                 :: "r"(dst), "l"(src) : "memory");
}
#define CP_COMMIT() asm volatile("cp.async.commit_group;" ::: "memory")
#define CP_WAIT0()  asm volatile("cp.async.wait_group 0;" ::: "memory")

// f16 mma m16n8k16, f32 accumulate. A row-major (16x16), B col-major (16x8).
__device__ __forceinline__ void mma_f16(float* d, const uint32_t* a, const uint32_t* b) {
    asm volatile(
        "mma.sync.aligned.m16n8k16.row.col.f32.f16.f16.f32 "
        "{%0,%1,%2,%3}, {%4,%5,%6,%7}, {%8,%9}, {%0,%1,%2,%3};"
        : "+f"(d[0]), "+f"(d[1]), "+f"(d[2]), "+f"(d[3])
        : "r"(a[0]), "r"(a[1]), "r"(a[2]), "r"(a[3]), "r"(b[0]), "r"(b[1]));
}

__device__ __forceinline__ void ldmatrix_x4(
    uint32_t& r0, uint32_t& r1, uint32_t& r2, uint32_t& r3, uint32_t addr)
{
    asm volatile("ldmatrix.sync.aligned.m8n8.x4.shared.b16 {%0,%1,%2,%3}, [%4];"
                 : "=r"(r0), "=r"(r1), "=r"(r2), "=r"(r3) : "r"(addr));
}
__device__ __forceinline__ void ldmatrix_x4_trans(
    uint32_t& r0, uint32_t& r1, uint32_t& r2, uint32_t& r3, uint32_t addr)
{
    asm volatile("ldmatrix.sync.aligned.m8n8.x4.trans.shared.b16 {%0,%1,%2,%3}, [%4];"
                 : "=r"(r0), "=r"(r1), "=r"(r2), "=r"(r3) : "r"(addr));
}

__device__ __forceinline__ uint32_t packh2(float x, float y) {
    __half2 h = __floats2half2_rn(x, y);
    return *reinterpret_cast<uint32_t*>(&h);
}
__device__ __forceinline__ uint32_t ldh2(const __half* p) {
    return *reinterpret_cast<const uint32_t*>(p);
}

// ---------------------------------------------------------------------------
// Streaming f32 -> f16 convert for the 6 weights (NO transpose; native [K,N]).
// All six weight tensors have exactly WSZ elements.
// ---------------------------------------------------------------------------
__global__ void conv_w(const float* __restrict__ Wq1, const float* __restrict__ Wk1,
                       const float* __restrict__ Wv1, const float* __restrict__ Wk2,
                       const float* __restrict__ Wv2, const float* __restrict__ Wo,
                       __half* __restrict__ wt)
{
    const int z = blockIdx.z;
    const float* src = (z == 0) ? Wq1 : (z == 1) ? Wk1 : (z == 2) ? Wv1
                     : (z == 3) ? Wk2 : (z == 4) ? Wv2 : Wo;
    __half* dst = wt + (size_t)z * WSZ;
    const size_t n4 = WSZ / 4;    // 131072 float4s
    for (size_t i = (size_t)blockIdx.x * blockDim.x + threadIdx.x;
         i < n4; i += (size_t)gridDim.x * blockDim.x) {
        const float4 v = ((const float4*)src)[i];
        uint2 o;
        o.x = packh2(v.x, v.y);
        o.y = packh2(v.z, v.w);
        ((uint2*)dst)[i] = o;
    }
}

// ---------------------------------------------------------------------------
// Convert x1, x2 to f16 into g_xr
// ---------------------------------------------------------------------------
#define XF4 ((size_t)MTOT * D / 4)
__global__ void conv_x(const float* __restrict__ x1, const float* __restrict__ x2,
                       __half* __restrict__ xr)
{
    const size_t total = 2 * XF4;
    for (size_t i = (size_t)blockIdx.x * blockDim.x + threadIdx.x;
         i < total; i += (size_t)gridDim.x * blockDim.x) {
        const float4 v = (i < XF4) ? ((const float4*)x1)[i] : ((const float4*)x2)[i - XF4];
        uint2 o;
        o.x = packh2(v.x, v.y);
        o.y = packh2(v.z, v.w);
        ((uint2*)xr)[i] = o;
    }
}

// ---------------------------------------------------------------------------
// cp.async double-buffered f16 GEMM core (128x128, BK=32, 8 warps).
// A [m][K] f16 (native), W [K][N] f16 (native).
// A-frags via ldmatrix.x4 (pitch KP=40); B-frags via ldmatrix.x4.trans from
// a [32 k][128 n] tile (pitch NPITCH=136 -> trans rows on distinct banks).
// ---------------------------------------------------------------------------
#define KP 40
#define ABUF_H (128 * KP)               // 5120 halves
#define NPITCH 136
#define BBUF_H (32 * NPITCH)            // 4352 halves
#define GSTG_H (ABUF_H + BBUF_H)        // stage halves (9472)

__device__ __forceinline__ void gemm_core(
    const __half* __restrict__ A, const __half* __restrict__ W,
    void* __restrict__ C, const float* __restrict__ bias,
    int K, int N, size_t cstride, size_t coff, float scale, bool outHalf)
{
    extern __shared__ __half gsm[];

    const int tid = threadIdx.x;
    const int w = tid >> 5, lane = tid & 31;
    const int g = lane >> 2, tg = lane & 3;
    const int wm = (w & 1) * 64, wn = (w >> 1) * 32;
    const int m0 = blockIdx.y * 128, n0 = blockIdx.x * 128;

    // A loader: row lr (0..127), half-offset lc in {0,16}
    const int lr = tid >> 1;
    const int lc = (tid & 1) * 16;
    // B loader: k-row br (0..31), half-offset bc in {0,16,...,112}
    const int br = tid >> 3;
    const int bc = (tid & 7) * 16;

    const __half* Ag = A + (size_t)(m0 + lr) * K + lc;
    const __half* Bg = W + (size_t)br * N + n0 + bc;

    const uint32_t smb  = smem_u32(gsm);
    const uint32_t offA = (uint32_t)(lr * KP + lc) * 2;
    const uint32_t offB = (uint32_t)(ABUF_H + br * NPITCH + bc) * 2;

    // ldmatrix lane roles
    const int sub = lane >> 3, rw = lane & 7;
    const int a_roff = (sub & 1) * 8, a_koff = (sub >> 1) * 8;
    const int t_vr  = (sub & 1) * 8 + rw;    // trans: row within k16 slice
    const int t_vcb = (sub >> 1) * 8;        // trans: col offset in 16-n pair

    #pragma unroll
    for (int c = 0; c < 2; c++) {
        cpasync16(smb + offA + 16 * c, Ag + 8 * c);
        cpasync16(smb + offB + 16 * c, Bg + 8 * c);
    }
    CP_COMMIT();

    float acc[4][4][4] = {};
    const int S = K >> 5;
    for (int s = 0; s < S; s++) {
        CP_WAIT0();
        __syncthreads();
        if (s + 1 < S) {
            const uint32_t sb = smb + (uint32_t)(((s + 1) & 1) * GSTG_H) * 2;
            const __half* Ag2 = Ag + (size_t)(s + 1) * 32;
            const __half* Bg2 = Bg + (size_t)(s + 1) * 32 * N;
            #pragma unroll
            for (int c = 0; c < 2; c++) {
                cpasync16(sb + offA + 16 * c, Ag2 + 8 * c);
                cpasync16(sb + offB + 16 * c, Bg2 + 8 * c);
            }
            CP_COMMIT();
        }
        const uint32_t asb = smb + (uint32_t)((s & 1) * GSTG_H) * 2;
        const uint32_t bsb = asb + ABUF_H * 2;

        #pragma unroll
        for (int ks = 0; ks < 2; ks++) {          // two k16 slices
            const int k0 = 16 * ks;
            uint32_t af[4][4], bf[4][2];
            #pragma unroll
            for (int mt = 0; mt < 4; mt++) {
                const uint32_t aa = asb +
                    (uint32_t)((wm + 16 * mt + a_roff + rw) * KP + k0 + a_koff) * 2;
                ldmatrix_x4(af[mt][0], af[mt][1], af[mt][2], af[mt][3], aa);
            }
            #pragma unroll
            for (int np = 0; np < 2; np++) {      // 16-n pairs (trans)
                const uint32_t ba = bsb +
                    (uint32_t)((k0 + t_vr) * NPITCH + wn + 16 * np + t_vcb) * 2;
                ldmatrix_x4_trans(bf[2 * np][0], bf[2 * np][1],
                                  bf[2 * np + 1][0], bf[2 * np + 1][1], ba);
            }
            #pragma unroll
            for (int mt = 0; mt < 4; mt++)
                #pragma unroll
                for (int nt = 0; nt < 4; nt++)
                    mma_f16(acc[mt][nt], af[mt], bf[nt]);
        }
    }

    #pragma unroll
    for (int mt = 0; mt < 4; mt++) {
        const size_t r0 = (size_t)(m0 + wm + 16 * mt + g);
        const size_t r1 = r0 + 8;
        const size_t o0 = (r0 >> 11) * cstride + (r0 & 2047) * N + coff;
        const size_t o1 = (r1 >> 11) * cstride + (r1 & 2047) * N + coff;
        #pragma unroll
        for (int nt = 0; nt < 4; nt++) {
            const int cc = n0 + wn + 8 * nt + 2 * tg;
            float v00 = acc[mt][nt][0] * scale;
            float v01 = acc[mt][nt][1] * scale;
            float v10 = acc[mt][nt][2] * scale;
            float v11 = acc[mt][nt][3] * scale;
            if (outHalf) {
                *(uint32_t*)((__half*)C + o0 + cc) = packh2(v00, v01);
                *(uint32_t*)((__half*)C + o1 + cc) = packh2(v10, v11);
            } else {
                const float bx = bias ? bias[cc] : 0.f;
                const float by = bias ? bias[cc + 1] : 0.f;
                *(float2*)((float*)C + o0 + cc) = make_float2(v00 + bx, v01 + by);
                *(float2*)((float*)C + o1 + cc) = make_float2(v10 + bx, v11 + by);
            }
        }
    }
}

__global__ __launch_bounds__(256, 2)
void gemm5(const __half* __restrict__ x1r, const __half* __restrict__ x2r,
           const __half* __restrict__ wt,
           __half* __restrict__ q1, __half* __restrict__ k, __half* __restrict__ v)
{
    const int z = blockIdx.z;
    const __half* A = (z < 3) ? x1r : x2r;
    const __half* W = wt + (size_t)z * WSZ;
    const size_t kvs  = (size_t)NKV * INNER;
    const size_t off2 = (size_t)N1 * INNER;
    __half* Cp; size_t cs, co; float sc;
    if (z == 0)      { Cp = q1; cs = (size_t)N1 * INNER; co = 0;    sc = SCALE_Q; }
    else if (z == 1) { Cp = k;  cs = kvs;                co = 0;    sc = 1.f; }
    else if (z == 2) { Cp = v;  cs = kvs;                co = 0;    sc = 1.f; }
    else if (z == 3) { Cp = k;  cs = kvs;                co = off2; sc = 1.f; }
    else             { Cp = v;  cs = kvs;                co = off2; sc = 1.f; }
    gemm_core(A, W, Cp, nullptr, D, INNER, cs, co, sc, true);
}

__global__ __launch_bounds__(256, 2)
void gemmO(const __half* __restrict__ ao, const __half* __restrict__ wt5,
           float* __restrict__ out, const float* __restrict__ bo)
{
    gemm_core(ao, wt5, out, bo, INNER, D, (size_t)N1 * D, 0, 1.f, false);
}

// ---------------------------------------------------------------------------
// Flash attention v7 (unchanged from R11): split-KV x4, all-f16 MMA.
// ---------------------------------------------------------------------------
#define APH 72
#define KV_H   (64 * APH)           // halves per K (or V) tile
#define FBUF_H (2 * KV_H)           // halves per stage (K+V)

__global__ __launch_bounds__(256, 2)
void flash7(const __half* __restrict__ q, const __half* __restrict__ kc,
            const __half* __restrict__ vc,
            __half* __restrict__ aop, float2* __restrict__ ml)
{
    extern __shared__ __half fsm[];

    const int z  = blockIdx.z;
    const int b  = z >> 2;            // NSPLIT == 4
    const int sp = z & 3;
    const int h  = blockIdx.y;
    const int qt = blockIdx.x;
    const int tid  = threadIdx.x;
    const int w = tid >> 5, lane = tid & 31;
    const int g = lane >> 2, tg = lane & 3;
    const int m0 = 16 * w;

    const __half* qb = q  + ((size_t)b * N1 + (size_t)qt * 128) * INNER + h * DHEAD;
    const __half* kb = kc + ((size_t)b * NKV + (size_t)sp * KVS) * INNER + h * DHEAD;
    const __half* vb = vc + ((size_t)b * NKV + (size_t)sp * KVS) * INNER + h * DHEAD;

    const uint32_t smb = smem_u32(fsm);

    const int cr = tid >> 2;
    const int cc0 = (tid & 3) * 16;

    {
        const uint32_t kdst = smb + (uint32_t)(cr * APH + cc0) * 2;
        const uint32_t vdst = kdst + KV_H * 2;
        const __half* ks = kb + (size_t)cr * INNER + cc0;
        const __half* vs = vb + (size_t)cr * INNER + cc0;
        #pragma unroll
        for (int c = 0; c < 2; c++) {
            cpasync16(kdst + 16 * c, ks + 8 * c);
            cpasync16(vdst + 16 * c, vs + 8 * c);
        }
    }
    CP_COMMIT();

    uint32_t qaf[4][4];
    {
        const __half* q0 = qb + (size_t)(m0 + g) * INNER;
        const __half* q1r = q0 + 8 * INNER;
        #pragma unroll
        for (int s = 0; s < 4; s++) {
            qaf[s][0] = ldh2(q0  + 16 * s + 2 * tg);
            qaf[s][1] = ldh2(q1r + 16 * s + 2 * tg);
            qaf[s][2] = ldh2(q0  + 16 * s + 2 * tg + 8);
            qaf[s][3] = ldh2(q1r + 16 * s + 2 * tg + 8);
        }
    }

    float accO[8][4] = {};
    float mrun0 = -1e30f, mrun1 = -1e30f, lrun0 = 0.f, lrun1 = 0.f;

    const int sub = lane >> 3, rw = lane & 7;
    const int k_roff = (sub >> 1) * 8, k_koff = (sub & 1) * 8;
    const int vr = (sub & 1) * 8 + rw;
    const int vcb = (sub >> 1) * 8;

    const int NT = KVS / 64;     // 16
    for (int j = 0; j < NT; j++) {
        CP_WAIT0();
        __syncthreads();

        if (j + 1 < NT) {
            const uint32_t base = smb + (uint32_t)(((j + 1) & 1) * FBUF_H) * 2;
            const uint32_t kdst = base + (uint32_t)(cr * APH + cc0) * 2;
            const uint32_t vdst = kdst + KV_H * 2;
            const __half* ks = kb + (size_t)(j + 1) * 64 * INNER + (size_t)cr * INNER + cc0;
            const __half* vs = vb + (size_t)(j + 1) * 64 * INNER + (size_t)cr * INNER + cc0;
            #pragma unroll
            for (int c = 0; c < 2; c++) {
                cpasync16(kdst + 16 * c, ks + 8 * c);
                cpasync16(vdst + 16 * c, vs + 8 * c);
            }
            CP_COMMIT();
        }

        const uint32_t ksb = smb + (uint32_t)((j & 1) * FBUF_H) * 2;
        const uint32_t vsb = ksb + KV_H * 2;

        float sacc[8][4] = {};
        #pragma unroll
        for (int ks = 0; ks < 4; ks++) {
            const int k0 = 16 * ks;
            #pragma unroll
            for (int np = 0; np < 4; np++) {
                uint32_t b0, b1, b2, b3;
                const uint32_t ka = ksb +
                    (uint32_t)((16 * np + k_roff + rw) * APH + k0 + k_koff) * 2;
                ldmatrix_x4(b0, b1, b2, b3, ka);
                uint32_t bf0[2] = { b0, b1 };
                uint32_t bf1[2] = { b2, b3 };
                mma_f16(sacc[2 * np],     qaf[ks], bf0);
                mma_f16(sacc[2 * np + 1], qaf[ks], bf1);
            }
        }

        float rm0 = -1e30f, rm1 = -1e30f;
        #pragma unroll
        for (int nt = 0; nt < 8; nt++) {
            rm0 = fmaxf(rm0, fmaxf(sacc[nt][0], sacc[nt][1]));
            rm1 = fmaxf(rm1, fmaxf(sacc[nt][2], sacc[nt][3]));
        }
        #pragma unroll
        for (int off = 1; off <= 2; off <<= 1) {
            rm0 = fmaxf(rm0, __shfl_xor_sync(0xFFFFFFFFu, rm0, off));
            rm1 = fmaxf(rm1, __shfl_xor_sync(0xFFFFFFFFu, rm1, off));
        }
        const float mn0 = fmaxf(mrun0, rm0);
        const float mn1 = fmaxf(mrun1, rm1);
        const float al0 = exp2f(mrun0 - mn0);
        const float al1 = exp2f(mrun1 - mn1);

        float rs0 = 0.f, rs1 = 0.f;
        uint32_t paf[4][4];
        #pragma unroll
        for (int ks = 0; ks < 4; ks++) {
            const int e0 = 2 * ks, e1 = 2 * ks + 1;
            float p00 = exp2f(sacc[e0][0] - mn0);
            float p01 = exp2f(sacc[e0][1] - mn0);
            float p10 = exp2f(sacc[e0][2] - mn1);
            float p11 = exp2f(sacc[e0][3] - mn1);
            float p20 = exp2f(sacc[e1][0] - mn0);
            float p21 = exp2f(sacc[e1][1] - mn0);
            float p30 = exp2f(sacc[e1][2] - mn1);
            float p31 = exp2f(sacc[e1][3] - mn1);
            rs0 += p00 + p01 + p20 + p21;
            rs1 += p10 + p11 + p30 + p31;
            paf[ks][0] = packh2(p00, p01);
            paf[ks][1] = packh2(p10, p11);
            paf[ks][2] = packh2(p20, p21);
            paf[ks][3] = packh2(p30, p31);
        }
        #pragma unroll
        for (int off = 1; off <= 2; off <<= 1) {
            rs0 += __shfl_xor_sync(0xFFFFFFFFu, rs0, off);
            rs1 += __shfl_xor_sync(0xFFFFFFFFu, rs1, off);
        }
        lrun0 = lrun0 * al0 + rs0;
        lrun1 = lrun1 * al1 + rs1;
        mrun0 = mn0;
        mrun1 = mn1;

        if (!__all_sync(0xFFFFFFFFu, (al0 == 1.f) && (al1 == 1.f))) {
            #pragma unroll
            for (int nt = 0; nt < 8; nt++) {
                accO[nt][0] *= al0; accO[nt][1] *= al0;
                accO[nt][2] *= al1; accO[nt][3] *= al1;
            }
        }

        #pragma unroll
        for (int ks = 0; ks < 4; ks++) {
            #pragma unroll
            for (int dp = 0; dp < 4; dp++) {
                uint32_t r0, r1, r2, r3;
                const uint32_t addr = vsb +
                    (uint32_t)((16 * ks + vr) * APH + 16 * dp + vcb) * 2;
                ldmatrix_x4_trans(r0, r1, r2, r3, addr);
                uint32_t bf0[2] = { r0, r1 };
                uint32_t bf1[2] = { r2, r3 };
                mma_f16(accO[2 * dp],     paf[ks], bf0);
                mma_f16(accO[2 * dp + 1], paf[ks], bf1);
            }
        }
    }

    {
        const int qr0 = qt * 128 + m0 + g;
        __half* d0 = aop + (size_t)sp * PBUF
                   + ((size_t)b * N1 + qr0) * INNER + h * DHEAD;
        __half* d1 = d0 + 8 * INNER;
        #pragma unroll
        for (int nt = 0; nt < 8; nt++) {
            const int cc = 8 * nt + 2 * tg;
            *(uint32_t*)(d0 + cc) = packh2(accO[nt][0], accO[nt][1]);
            *(uint32_t*)(d1 + cc) = packh2(accO[nt][2], accO[nt][3]);
        }
        if (tg == 0) {
            float2* mlp = ml + (size_t)sp * MBUF
                        + ((size_t)b * HEADS + h) * N1;
            mlp[qr0]     = make_float2(mrun0, lrun0);
            mlp[qr0 + 8] = make_float2(mrun1, lrun1);
        }
    }
}

// ---------------------------------------------------------------------------
// Combine NSPLIT partials (unchanged from R11).
// ---------------------------------------------------------------------------
__global__ __launch_bounds__(256)
void combine4(const __half* __restrict__ aop, const float2* __restrict__ ml,
              __half* __restrict__ ao)
{
    const int bid = blockIdx.x;
    const int b   = bid >> 11;           // N1 == 2048
    const int row = bid & 2047;
    const int t   = threadIdx.x;
    const int h   = t >> 5;
    const int d   = (t & 31) * 2;

    const size_t mlIdx = ((size_t)b * HEADS + h) * N1 + row;
    float2 m0 = ml[0 * MBUF + mlIdx];
    float2 m1 = ml[1 * MBUF + mlIdx];
    float2 m2 = ml[2 * MBUF + mlIdx];
    float2 m3 = ml[3 * MBUF + mlIdx];

    const float mm = fmaxf(fmaxf(m0.x, m1.x), fmaxf(m2.x, m3.x));
    const float w0 = exp2f(m0.x - mm);
    const float w1 = exp2f(m1.x - mm);
    const float w2 = exp2f(m2.x - mm);
    const float w3 = exp2f(m3.x - mm);
    const float inv = 1.0f / (w0 * m0.y + w1 * m1.y + w2 * m2.y + w3 * m3.y);

    const size_t ofs = ((size_t)b * N1 + row) * INNER + h * DHEAD + d;
    const __half2 o0 = *(const __half2*)(aop + 0 * PBUF + ofs);
    const __half2 o1 = *(const __half2*)(aop + 1 * PBUF + ofs);
    const __half2 o2 = *(const __half2*)(aop + 2 * PBUF + ofs);
    const __half2 o3 = *(const __half2*)(aop + 3 * PBUF + ofs);

    const float2 f0 = __half22float2(o0);
    const float2 f1 = __half22float2(o1);
    const float2 f2 = __half22float2(o2);
    const float2 f3 = __half22float2(o3);

    const float ox = (w0 * f0.x + w1 * f1.x + w2 * f2.x + w3 * f3.x) * inv;
    const float oy = (w0 * f0.y + w1 * f1.y + w2 * f2.y + w3 * f3.y) * inv;
    *(uint32_t*)(ao + ofs) = packh2(ox, oy);
}

// ---------------------------------------------------------------------------
// Launch
// ---------------------------------------------------------------------------
extern "C" void kernel_launch(void* const* d_in, const int* in_sizes, int n_in,
                              void* d_out, int out_size)
{
    (void)in_sizes; (void)n_in; (void)out_size;

    const float* x1  = (const float*)d_in[0];
    const float* x2  = (const float*)d_in[1];
    const float* Wq1 = (const float*)d_in[2];
    const float* Wk1 = (const float*)d_in[3];
    const float* Wv1 = (const float*)d_in[4];
    const float* Wk2 = (const float*)d_in[5];
    const float* Wv2 = (const float*)d_in[6];
    const float* Wo  = (const float*)d_in[7];
    const float* bo  = (const float*)d_in[8];
    float* out = (float*)d_out;

    __half *q1, *kbuf, *vbuf, *aobuf, *wt, *xr, *aop;
    float2* mlb;
    cudaGetSymbolAddress((void**)&q1,    g_q1);
    cudaGetSymbolAddress((void**)&kbuf,  g_k);
    cudaGetSymbolAddress((void**)&vbuf,  g_v);
    cudaGetSymbolAddress((void**)&aobuf, g_ao);
    cudaGetSymbolAddress((void**)&wt,    g_wt);
    cudaGetSymbolAddress((void**)&xr,    g_xr);
    cudaGetSymbolAddress((void**)&aop,   g_aop);
    cudaGetSymbolAddress((void**)&mlb,   g_ml);

    const int gemm_smem  = 2 * GSTG_H * (int)sizeof(__half);  // 37888
    const int flash_smem = 2 * FBUF_H * (int)sizeof(__half);  // 36864
    cudaFuncSetAttribute(gemm5,  cudaFuncAttributeMaxDynamicSharedMemorySize, gemm_smem);
    cudaFuncSetAttribute(gemmO,  cudaFuncAttributeMaxDynamicSharedMemorySize, gemm_smem);
    cudaFuncSetAttribute(flash7, cudaFuncAttributeMaxDynamicSharedMemorySize, flash_smem);

    conv_w<<<dim3(128, 1, 6), 256>>>(Wq1, Wk1, Wv1, Wk2, Wv2, Wo, wt);
    conv_x<<<4096, 256>>>(x1, x2, xr);

    gemm5<<<dim3(INNER / 128, MTOT / 128, 5), 256, gemm_smem>>>(
        xr, xr + (size_t)MTOT * D, wt, q1, kbuf, vbuf);

    flash7<<<dim3(N1 / 128, HEADS, B * NSPLIT), 256, flash_smem>>>(
        q1, kbuf, vbuf, aop, mlb);

    combine4<<<B * N1, 256>>>(aop, mlb, aobuf);

    gemmO<<<dim3(D / 128, MTOT / 128, 1), 256, gemm_smem>>>(aobuf, wt + 5 * WSZ, out, bo);
}

// round 13
// speedup vs baseline: 1.1314x; 1.0071x over previous
#include <cuda_runtime.h>
#include <cuda_fp16.h>
#include <cstddef>
#include <cstdint>

// ---------------------------------------------------------------------------
// Problem constants
// ---------------------------------------------------------------------------
#define B     4
#define N1    2048
#define N2    2048
#define D     1024
#define HEADS 8
#define DHEAD 64
#define INNER (HEADS * DHEAD)     // 512
#define NKV   (N1 + N2)           // 4096
#define MTOT  (B * N1)            // 8192
#define NSPLIT 4
#define KVS   (NKV / NSPLIT)      // 1024 keys per split

#define SCALE_Q 0.18033688011112042f   // 0.125 * log2(e)

// Scratch (device globals — no allocation allowed), all fp16
__device__ __half g_q1[(size_t)B * N1 * INNER];
__device__ __half g_k [(size_t)B * NKV * INNER];
__device__ __half g_v [(size_t)B * NKV * INNER];
__device__ __half g_ao[(size_t)B * N1 * INNER];
#define WSZ (1024 * 512)
__device__ __half g_wt[6 * WSZ];                  // f16 weights, NATIVE [K,N]
__device__ __half g_xr[2 * (size_t)MTOT * D];     // converted x1,x2
// split-KV partials
#define PBUF ((size_t)B * N1 * INNER)
#define MBUF (B * HEADS * N1)
__device__ __half g_aop[NSPLIT * PBUF];           // unnormalized O partials
__device__ float2 g_ml [NSPLIT * MBUF];           // per-row (m, l), log2 domain

// ---------------------------------------------------------------------------
// PTX helpers (baseline sm_80-level only — safe for compute_103 target)
// ---------------------------------------------------------------------------
__device__ __forceinline__ uint32_t smem_u32(const void* p) {
    uint32_t a;
    asm("{ .reg .u64 t; cvta.to.shared.u64 t, %1; cvt.u32.u64 %0, t; }"
        : "=r"(a) : "l"(p));
    return a;
}
__device__ __forceinline__ void cpasync16(uint32_t dst, const void* src) {
    asm volatile("cp.async.cg.shared.global [%0], [%1], 16;"
                 :: "r"(dst), "l"(src) : "memory");
}
#define CP_COMMIT() asm volatile("cp.async.commit_group;" ::: "memory")
#define CP_WAIT0()  asm volatile("cp.async.wait_group 0;" ::: "memory")
#define CP_WAIT2()  asm volatile("cp.async.wait_group 2;" ::: "memory")

// f16 mma m16n8k16, f32 accumulate. A row-major (16x16), B col-major (16x8).
__device__ __forceinline__ void mma_f16(float* d, const uint32_t* a, const uint32_t* b) {
    asm volatile(
        "mma.sync.aligned.m16n8k16.row.col.f32.f16.f16.f32 "
        "{%0,%1,%2,%3}, {%4,%5,%6,%7}, {%8,%9}, {%0,%1,%2,%3};"
        : "+f"(d[0]), "+f"(d[1]), "+f"(d[2]), "+f"(d[3])
        : "r"(a[0]), "r"(a[1]), "r"(a[2]), "r"(a[3]), "r"(b[0]), "r"(b[1]));
}

__device__ __forceinline__ void ldmatrix_x4(
    uint32_t& r0, uint32_t& r1, uint32_t& r2, uint32_t& r3, uint32_t addr)
{
    asm volatile("ldmatrix.sync.aligned.m8n8.x4.shared.b16 {%0,%1,%2,%3}, [%4];"
                 : "=r"(r0), "=r"(r1), "=r"(r2), "=r"(r3) : "r"(addr));
}
__device__ __forceinline__ void ldmatrix_x4_trans(
    uint32_t& r0, uint32_t& r1, uint32_t& r2, uint32_t& r3, uint32_t addr)
{
    asm volatile("ldmatrix.sync.aligned.m8n8.x4.trans.shared.b16 {%0,%1,%2,%3}, [%4];"
                 : "=r"(r0), "=r"(r1), "=r"(r2), "=r"(r3) : "r"(addr));
}

__device__ __forceinline__ uint32_t packh2(float x, float y) {
    __half2 h = __floats2half2_rn(x, y);
    return *reinterpret_cast<uint32_t*>(&h);
}
__device__ __forceinline__ uint32_t ldh2(const __half* p) {
    return *reinterpret_cast<const uint32_t*>(p);
}

// ---------------------------------------------------------------------------
// Streaming f32 -> f16 convert for the 6 weights (NO transpose; native [K,N]).
// ---------------------------------------------------------------------------
__global__ void conv_w(const float* __restrict__ Wq1, const float* __restrict__ Wk1,
                       const float* __restrict__ Wv1, const float* __restrict__ Wk2,
                       const float* __restrict__ Wv2, const float* __restrict__ Wo,
                       __half* __restrict__ wt)
{
    const int z = blockIdx.z;
    const float* src = (z == 0) ? Wq1 : (z == 1) ? Wk1 : (z == 2) ? Wv1
                     : (z == 3) ? Wk2 : (z == 4) ? Wv2 : Wo;
    __half* dst = wt + (size_t)z * WSZ;
    const size_t n4 = WSZ / 4;
    for (size_t i = (size_t)blockIdx.x * blockDim.x + threadIdx.x;
         i < n4; i += (size_t)gridDim.x * blockDim.x) {
        const float4 v = ((const float4*)src)[i];
        uint2 o;
        o.x = packh2(v.x, v.y);
        o.y = packh2(v.z, v.w);
        ((uint2*)dst)[i] = o;
    }
}

// ---------------------------------------------------------------------------
// Convert x1, x2 to f16 into g_xr
// ---------------------------------------------------------------------------
#define XF4 ((size_t)MTOT * D / 4)
__global__ void conv_x(const float* __restrict__ x1, const float* __restrict__ x2,
                       __half* __restrict__ xr)
{
    const size_t total = 2 * XF4;
    for (size_t i = (size_t)blockIdx.x * blockDim.x + threadIdx.x;
         i < total; i += (size_t)gridDim.x * blockDim.x) {
        const float4 v = (i < XF4) ? ((const float4*)x1)[i] : ((const float4*)x2)[i - XF4];
        uint2 o;
        o.x = packh2(v.x, v.y);
        o.y = packh2(v.z, v.w);
        ((uint2*)xr)[i] = o;
    }
}

// ---------------------------------------------------------------------------
// cp.async double-buffered f16 GEMM core (128x128, BK=32, 8 warps)  [R12]
// A-frags via ldmatrix.x4 (pitch KP=40); B-frags via ldmatrix.x4.trans from
// a [32 k][128 n] tile (pitch NPITCH=136).
// ---------------------------------------------------------------------------
#define KP 40
#define ABUF_H (128 * KP)               // 5120 halves
#define NPITCH 136
#define BBUF_H (32 * NPITCH)            // 4352 halves
#define GSTG_H (ABUF_H + BBUF_H)        // stage halves (9472)

__device__ __forceinline__ void gemm_core(
    const __half* __restrict__ A, const __half* __restrict__ W,
    void* __restrict__ C, const float* __restrict__ bias,
    int K, int N, size_t cstride, size_t coff, float scale, bool outHalf)
{
    extern __shared__ __half gsm[];

    const int tid = threadIdx.x;
    const int w = tid >> 5, lane = tid & 31;
    const int g = lane >> 2, tg = lane & 3;
    const int wm = (w & 1) * 64, wn = (w >> 1) * 32;
    const int m0 = blockIdx.y * 128, n0 = blockIdx.x * 128;

    const int lr = tid >> 1;
    const int lc = (tid & 1) * 16;
    const int br = tid >> 3;
    const int bc = (tid & 7) * 16;

    const __half* Ag = A + (size_t)(m0 + lr) * K + lc;
    const __half* Bg = W + (size_t)br * N + n0 + bc;

    const uint32_t smb  = smem_u32(gsm);
    const uint32_t offA = (uint32_t)(lr * KP + lc) * 2;
    const uint32_t offB = (uint32_t)(ABUF_H + br * NPITCH + bc) * 2;

    const int sub = lane >> 3, rw = lane & 7;
    const int a_roff = (sub & 1) * 8, a_koff = (sub >> 1) * 8;
    const int t_vr  = (sub & 1) * 8 + rw;
    const int t_vcb = (sub >> 1) * 8;

    #pragma unroll
    for (int c = 0; c < 2; c++) {
        cpasync16(smb + offA + 16 * c, Ag + 8 * c);
        cpasync16(smb + offB + 16 * c, Bg + 8 * c);
    }
    CP_COMMIT();

    float acc[4][4][4] = {};
    const int S = K >> 5;
    for (int s = 0; s < S; s++) {
        CP_WAIT0();
        __syncthreads();
        if (s + 1 < S) {
            const uint32_t sb = smb + (uint32_t)(((s + 1) & 1) * GSTG_H) * 2;
            const __half* Ag2 = Ag + (size_t)(s + 1) * 32;
            const __half* Bg2 = Bg + (size_t)(s + 1) * 32 * N;
            #pragma unroll
            for (int c = 0; c < 2; c++) {
                cpasync16(sb + offA + 16 * c, Ag2 + 8 * c);
                cpasync16(sb + offB + 16 * c, Bg2 + 8 * c);
            }
            CP_COMMIT();
        }
        const uint32_t asb = smb + (uint32_t)((s & 1) * GSTG_H) * 2;
        const uint32_t bsb = asb + ABUF_H * 2;

        #pragma unroll
        for (int ks = 0; ks < 2; ks++) {
            const int k0 = 16 * ks;
            uint32_t af[4][4], bf[4][2];
            #pragma unroll
            for (int mt = 0; mt < 4; mt++) {
                const uint32_t aa = asb +
                    (uint32_t)((wm + 16 * mt + a_roff + rw) * KP + k0 + a_koff) * 2;
                ldmatrix_x4(af[mt][0], af[mt][1], af[mt][2], af[mt][3], aa);
            }
            #pragma unroll
            for (int np = 0; np < 2; np++) {
                const uint32_t ba = bsb +
                    (uint32_t)((k0 + t_vr) * NPITCH + wn + 16 * np + t_vcb) * 2;
                ldmatrix_x4_trans(bf[2 * np][0], bf[2 * np][1],
                                  bf[2 * np + 1][0], bf[2 * np + 1][1], ba);
            }
            #pragma unroll
            for (int mt = 0; mt < 4; mt++)
                #pragma unroll
                for (int nt = 0; nt < 4; nt++)
                    mma_f16(acc[mt][nt], af[mt], bf[nt]);
        }
    }

    #pragma unroll
    for (int mt = 0; mt < 4; mt++) {
        const size_t r0 = (size_t)(m0 + wm + 16 * mt + g);
        const size_t r1 = r0 + 8;
        const size_t o0 = (r0 >> 11) * cstride + (r0 & 2047) * N + coff;
        const size_t o1 = (r1 >> 11) * cstride + (r1 & 2047) * N + coff;
        #pragma unroll
        for (int nt = 0; nt < 4; nt++) {
            const int cc = n0 + wn + 8 * nt + 2 * tg;
            float v00 = acc[mt][nt][0] * scale;
            float v01 = acc[mt][nt][1] * scale;
            float v10 = acc[mt][nt][2] * scale;
            float v11 = acc[mt][nt][3] * scale;
            if (outHalf) {
                *(uint32_t*)((__half*)C + o0 + cc) = packh2(v00, v01);
                *(uint32_t*)((__half*)C + o1 + cc) = packh2(v10, v11);
            } else {
                const float bx = bias ? bias[cc] : 0.f;
                const float by = bias ? bias[cc + 1] : 0.f;
                *(float2*)((float*)C + o0 + cc) = make_float2(v00 + bx, v01 + by);
                *(float2*)((float*)C + o1 + cc) = make_float2(v10 + bx, v11 + by);
            }
        }
    }
}

__global__ __launch_bounds__(256, 2)
void gemm5(const __half* __restrict__ x1r, const __half* __restrict__ x2r,
           const __half* __restrict__ wt,
           __half* __restrict__ q1, __half* __restrict__ k, __half* __restrict__ v)
{
    const int z = blockIdx.z;
    const __half* A = (z < 3) ? x1r : x2r;
    const __half* W = wt + (size_t)z * WSZ;
    const size_t kvs  = (size_t)NKV * INNER;
    const size_t off2 = (size_t)N1 * INNER;
    __half* Cp; size_t cs, co; float sc;
    if (z == 0)      { Cp = q1; cs = (size_t)N1 * INNER; co = 0;    sc = SCALE_Q; }
    else if (z == 1) { Cp = k;  cs = kvs;                co = 0;    sc = 1.f; }
    else if (z == 2) { Cp = v;  cs = kvs;                co = 0;    sc = 1.f; }
    else if (z == 3) { Cp = k;  cs = kvs;                co = off2; sc = 1.f; }
    else             { Cp = v;  cs = kvs;                co = off2; sc = 1.f; }
    gemm_core(A, W, Cp, nullptr, D, INNER, cs, co, sc, true);
}

__global__ __launch_bounds__(256, 2)
void gemmO(const __half* __restrict__ ao, const __half* __restrict__ wt5,
           float* __restrict__ out, const float* __restrict__ bo)
{
    gemm_core(ao, wt5, out, bo, INNER, D, (size_t)N1 * D, 0, 1.f, false);
}

// ---------------------------------------------------------------------------
// Flash attention v8: split-KV x4, 4-stage KV ring, ONE barrier per 2 tiles.
// ---------------------------------------------------------------------------
#define APH 72
#define KV_H   (64 * APH)           // halves per K (or V) tile
#define FBUF_H (2 * KV_H)           // halves per stage (K+V)

__global__ __launch_bounds__(256, 2)
void flash8(const __half* __restrict__ q, const __half* __restrict__ kc,
            const __half* __restrict__ vc,
            __half* __restrict__ aop, float2* __restrict__ ml)
{
    extern __shared__ __half fsm[];

    const int z  = blockIdx.z;
    const int b  = z >> 2;            // NSPLIT == 4
    const int sp = z & 3;
    const int h  = blockIdx.y;
    const int qt = blockIdx.x;
    const int tid  = threadIdx.x;
    const int w = tid >> 5, lane = tid & 31;
    const int g = lane >> 2, tg = lane & 3;
    const int m0 = 16 * w;

    const __half* qb = q  + ((size_t)b * N1 + (size_t)qt * 128) * INNER + h * DHEAD;
    const __half* kb = kc + ((size_t)b * NKV + (size_t)sp * KVS) * INNER + h * DHEAD;
    const __half* vb = vc + ((size_t)b * NKV + (size_t)sp * KVS) * INNER + h * DHEAD;

    const uint32_t smb = smem_u32(fsm);

    const int cr = tid >> 2;
    const int cc0 = (tid & 3) * 16;
    const uint32_t rowK = (uint32_t)(cr * APH + cc0) * 2;
    const uint32_t rowV = rowK + KV_H * 2;

    // --- preload KV tiles 0,1 into stages 0,1 ---
    #pragma unroll
    for (int s = 0; s < 2; s++) {
        const uint32_t sb = smb + (uint32_t)(s * FBUF_H) * 2;
        const __half* ks = kb + (size_t)s * 64 * INNER + (size_t)cr * INNER + cc0;
        const __half* vs = vb + (size_t)s * 64 * INNER + (size_t)cr * INNER + cc0;
        #pragma unroll
        for (int c = 0; c < 2; c++) {
            cpasync16(sb + rowK + 16 * c, ks + 8 * c);
            cpasync16(sb + rowV + 16 * c, vs + 8 * c);
        }
        CP_COMMIT();
    }

    // --- Q A-fragments from gmem ---
    uint32_t qaf[4][4];
    {
        const __half* q0 = qb + (size_t)(m0 + g) * INNER;
        const __half* q1r = q0 + 8 * INNER;
        #pragma unroll
        for (int s = 0; s < 4; s++) {
            qaf[s][0] = ldh2(q0  + 16 * s + 2 * tg);
            qaf[s][1] = ldh2(q1r + 16 * s + 2 * tg);
            qaf[s][2] = ldh2(q0  + 16 * s + 2 * tg + 8);
            qaf[s][3] = ldh2(q1r + 16 * s + 2 * tg + 8);
        }
    }

    float accO[8][4] = {};
    float mrun0 = -1e30f, mrun1 = -1e30f, lrun0 = 0.f, lrun1 = 0.f;

    const int sub = lane >> 3, rw = lane & 7;
    const int k_roff = (sub >> 1) * 8, k_koff = (sub & 1) * 8;
    const int vr = (sub & 1) * 8 + rw;
    const int vcb = (sub >> 1) * 8;

    const int NT = KVS / 64;     // 16
    for (int r = 0; r < NT / 2; r++) {
        __syncthreads();   // all warps done with tiles 2r-2, 2r-1 (stage reuse)

        const int jp0 = 2 * r + 2;
        if (jp0 < NT) {
            #pragma unroll
            for (int t = 0; t < 2; t++) {
                const int jp = jp0 + t;
                const uint32_t sb = smb + (uint32_t)((jp & 3) * FBUF_H) * 2;
                const __half* ks = kb + (size_t)jp * 64 * INNER + (size_t)cr * INNER + cc0;
                const __half* vs = vb + (size_t)jp * 64 * INNER + (size_t)cr * INNER + cc0;
                #pragma unroll
                for (int c = 0; c < 2; c++) {
                    cpasync16(sb + rowK + 16 * c, ks + 8 * c);
                    cpasync16(sb + rowV + 16 * c, vs + 8 * c);
                }
                CP_COMMIT();
            }
            CP_WAIT2();
        } else {
            CP_WAIT0();
        }

        #pragma unroll
        for (int t = 0; t < 2; t++) {
            const int j = 2 * r + t;
            const uint32_t ksb = smb + (uint32_t)((j & 3) * FBUF_H) * 2;
            const uint32_t vsb = ksb + KV_H * 2;

            // --- S = Q @ K^T ---
            float sacc[8][4] = {};
            #pragma unroll
            for (int ks = 0; ks < 4; ks++) {
                const int k0 = 16 * ks;
                #pragma unroll
                for (int np = 0; np < 4; np++) {
                    uint32_t b0, b1, b2, b3;
                    const uint32_t ka = ksb +
                        (uint32_t)((16 * np + k_roff + rw) * APH + k0 + k_koff) * 2;
                    ldmatrix_x4(b0, b1, b2, b3, ka);
                    uint32_t bf0[2] = { b0, b1 };
                    uint32_t bf1[2] = { b2, b3 };
                    mma_f16(sacc[2 * np],     qaf[ks], bf0);
                    mma_f16(sacc[2 * np + 1], qaf[ks], bf1);
                }
            }

            // --- register online softmax ---
            float rm0 = -1e30f, rm1 = -1e30f;
            #pragma unroll
            for (int nt = 0; nt < 8; nt++) {
                rm0 = fmaxf(rm0, fmaxf(sacc[nt][0], sacc[nt][1]));
                rm1 = fmaxf(rm1, fmaxf(sacc[nt][2], sacc[nt][3]));
            }
            #pragma unroll
            for (int off = 1; off <= 2; off <<= 1) {
                rm0 = fmaxf(rm0, __shfl_xor_sync(0xFFFFFFFFu, rm0, off));
                rm1 = fmaxf(rm1, __shfl_xor_sync(0xFFFFFFFFu, rm1, off));
            }
            const float mn0 = fmaxf(mrun0, rm0);
            const float mn1 = fmaxf(mrun1, rm1);
            const float al0 = exp2f(mrun0 - mn0);
            const float al1 = exp2f(mrun1 - mn1);

            float rs0 = 0.f, rs1 = 0.f;
            uint32_t paf[4][4];
            #pragma unroll
            for (int ks = 0; ks < 4; ks++) {
                const int e0 = 2 * ks, e1 = 2 * ks + 1;
                float p00 = exp2f(sacc[e0][0] - mn0);
                float p01 = exp2f(sacc[e0][1] - mn0);
                float p10 = exp2f(sacc[e0][2] - mn1);
                float p11 = exp2f(sacc[e0][3] - mn1);
                float p20 = exp2f(sacc[e1][0] - mn0);
                float p21 = exp2f(sacc[e1][1] - mn0);
                float p30 = exp2f(sacc[e1][2] - mn1);
                float p31 = exp2f(sacc[e1][3] - mn1);
                rs0 += p00 + p01 + p20 + p21;
                rs1 += p10 + p11 + p30 + p31;
                paf[ks][0] = packh2(p00, p01);
                paf[ks][1] = packh2(p10, p11);
                paf[ks][2] = packh2(p20, p21);
                paf[ks][3] = packh2(p30, p31);
            }
            #pragma unroll
            for (int off = 1; off <= 2; off <<= 1) {
                rs0 += __shfl_xor_sync(0xFFFFFFFFu, rs0, off);
                rs1 += __shfl_xor_sync(0xFFFFFFFFu, rs1, off);
            }
            lrun0 = lrun0 * al0 + rs0;
            lrun1 = lrun1 * al1 + rs1;
            mrun0 = mn0;
            mrun1 = mn1;

            if (!__all_sync(0xFFFFFFFFu, (al0 == 1.f) && (al1 == 1.f))) {
                #pragma unroll
                for (int nt = 0; nt < 8; nt++) {
                    accO[nt][0] *= al0; accO[nt][1] *= al0;
                    accO[nt][2] *= al1; accO[nt][3] *= al1;
                }
            }

            // --- O += P @ V ---
            #pragma unroll
            for (int ks = 0; ks < 4; ks++) {
                #pragma unroll
                for (int dp = 0; dp < 4; dp++) {
                    uint32_t r0, r1, r2, r3;
                    const uint32_t addr = vsb +
                        (uint32_t)((16 * ks + vr) * APH + 16 * dp + vcb) * 2;
                    ldmatrix_x4_trans(r0, r1, r2, r3, addr);
                    uint32_t bf0[2] = { r0, r1 };
                    uint32_t bf1[2] = { r2, r3 };
                    mma_f16(accO[2 * dp],     paf[ks], bf0);
                    mma_f16(accO[2 * dp + 1], paf[ks], bf1);
                }
            }
        }
    }

    // --- write UNNORMALIZED partial O (f16) + (m,l) per row ---
    {
        const int qr0 = qt * 128 + m0 + g;
        __half* d0 = aop + (size_t)sp * PBUF
                   + ((size_t)b * N1 + qr0) * INNER + h * DHEAD;
        __half* d1 = d0 + 8 * INNER;
        #pragma unroll
        for (int nt = 0; nt < 8; nt++) {
            const int cc = 8 * nt + 2 * tg;
            *(uint32_t*)(d0 + cc) = packh2(accO[nt][0], accO[nt][1]);
            *(uint32_t*)(d1 + cc) = packh2(accO[nt][2], accO[nt][3]);
        }
        if (tg == 0) {
            float2* mlp = ml + (size_t)sp * MBUF
                        + ((size_t)b * HEADS + h) * N1;
            mlp[qr0]     = make_float2(mrun0, lrun0);
            mlp[qr0 + 8] = make_float2(mrun1, lrun1);
        }
    }
}

// ---------------------------------------------------------------------------
// Combine NSPLIT partials (unchanged).
// ---------------------------------------------------------------------------
__global__ __launch_bounds__(256)
void combine4(const __half* __restrict__ aop, const float2* __restrict__ ml,
              __half* __restrict__ ao)
{
    const int bid = blockIdx.x;
    const int b   = bid >> 11;           // N1 == 2048
    const int row = bid & 2047;
    const int t   = threadIdx.x;
    const int h   = t >> 5;
    const int d   = (t & 31) * 2;

    const size_t mlIdx = ((size_t)b * HEADS + h) * N1 + row;
    float2 m0 = ml[0 * MBUF + mlIdx];
    float2 m1 = ml[1 * MBUF + mlIdx];
    float2 m2 = ml[2 * MBUF + mlIdx];
    float2 m3 = ml[3 * MBUF + mlIdx];

    const float mm = fmaxf(fmaxf(m0.x, m1.x), fmaxf(m2.x, m3.x));
    const float w0 = exp2f(m0.x - mm);
    const float w1 = exp2f(m1.x - mm);
    const float w2 = exp2f(m2.x - mm);
    const float w3 = exp2f(m3.x - mm);
    const float inv = 1.0f / (w0 * m0.y + w1 * m1.y + w2 * m2.y + w3 * m3.y);

    const size_t ofs = ((size_t)b * N1 + row) * INNER + h * DHEAD + d;
    const __half2 o0 = *(const __half2*)(aop + 0 * PBUF + ofs);
    const __half2 o1 = *(const __half2*)(aop + 1 * PBUF + ofs);
    const __half2 o2 = *(const __half2*)(aop + 2 * PBUF + ofs);
    const __half2 o3 = *(const __half2*)(aop + 3 * PBUF + ofs);

    const float2 f0 = __half22float2(o0);
    const float2 f1 = __half22float2(o1);
    const float2 f2 = __half22float2(o2);
    const float2 f3 = __half22float2(o3);

    const float ox = (w0 * f0.x + w1 * f1.x + w2 * f2.x + w3 * f3.x) * inv;
    const float oy = (w0 * f0.y + w1 * f1.y + w2 * f2.y + w3 * f3.y) * inv;
    *(uint32_t*)(ao + ofs) = packh2(ox, oy);
}

// ---------------------------------------------------------------------------
// Launch
// ---------------------------------------------------------------------------
extern "C" void kernel_launch(void* const* d_in, const int* in_sizes, int n_in,
                              void* d_out, int out_size)
{
    (void)in_sizes; (void)n_in; (void)out_size;

    const float* x1  = (const float*)d_in[0];
    const float* x2  = (const float*)d_in[1];
    const float* Wq1 = (const float*)d_in[2];
    const float* Wk1 = (const float*)d_in[3];
    const float* Wv1 = (const float*)d_in[4];
    const float* Wk2 = (const float*)d_in[5];
    const float* Wv2 = (const float*)d_in[6];
    const float* Wo  = (const float*)d_in[7];
    const float* bo  = (const float*)d_in[8];
    float* out = (float*)d_out;

    __half *q1, *kbuf, *vbuf, *aobuf, *wt, *xr, *aop;
    float2* mlb;
    cudaGetSymbolAddress((void**)&q1,    g_q1);
    cudaGetSymbolAddress((void**)&kbuf,  g_k);
    cudaGetSymbolAddress((void**)&vbuf,  g_v);
    cudaGetSymbolAddress((void**)&aobuf, g_ao);
    cudaGetSymbolAddress((void**)&wt,    g_wt);
    cudaGetSymbolAddress((void**)&xr,    g_xr);
    cudaGetSymbolAddress((void**)&aop,   g_aop);
    cudaGetSymbolAddress((void**)&mlb,   g_ml);

    const int gemm_smem  = 2 * GSTG_H * (int)sizeof(__half);  // 37888
    const int flash_smem = 4 * FBUF_H * (int)sizeof(__half);  // 73728
    cudaFuncSetAttribute(gemm5,  cudaFuncAttributeMaxDynamicSharedMemorySize, gemm_smem);
    cudaFuncSetAttribute(gemmO,  cudaFuncAttributeMaxDynamicSharedMemorySize, gemm_smem);
    cudaFuncSetAttribute(flash8, cudaFuncAttributeMaxDynamicSharedMemorySize, flash_smem);

    conv_w<<<dim3(128, 1, 6), 256>>>(Wq1, Wk1, Wv1, Wk2, Wv2, Wo, wt);
    conv_x<<<4096, 256>>>(x1, x2, xr);

    gemm5<<<dim3(INNER / 128, MTOT / 128, 5), 256, gemm_smem>>>(
        xr, xr + (size_t)MTOT * D, wt, q1, kbuf, vbuf);

    flash8<<<dim3(N1 / 128, HEADS, B * NSPLIT), 256, flash_smem>>>(
        q1, kbuf, vbuf, aop, mlb);

    combine4<<<B * N1, 256>>>(aop, mlb, aobuf);

    gemmO<<<dim3(D / 128, MTOT / 128, 1), 256, gemm_smem>>>(aobuf, wt + 5 * WSZ, out, bo);
}

// round 14
// speedup vs baseline: 1.1842x; 1.0466x over previous
#include <cuda_runtime.h>
#include <cuda_fp16.h>
#include <cstddef>
#include <cstdint>

// ---------------------------------------------------------------------------
// Problem constants
// ---------------------------------------------------------------------------
#define B     4
#define N1    2048
#define N2    2048
#define D     1024
#define HEADS 8
#define DHEAD 64
#define INNER (HEADS * DHEAD)     // 512
#define NKV   (N1 + N2)           // 4096
#define MTOT  (B * N1)            // 8192
#define NSPLIT 4
#define KVS   (NKV / NSPLIT)      // 1024 keys per split

#define SCALE_Q 0.18033688011112042f   // 0.125 * log2(e)

// Scratch (device globals — no allocation allowed), all fp16
__device__ __half g_q1[(size_t)B * N1 * INNER];
__device__ __half g_k [(size_t)B * NKV * INNER];
__device__ __half g_v [(size_t)B * NKV * INNER];
__device__ __half g_ao[(size_t)B * N1 * INNER];
#define WSZ (1024 * 512)
__device__ __half g_wt[6 * WSZ];                  // f16 weights, NATIVE [K,N]
__device__ __half g_xr[2 * (size_t)MTOT * D];     // converted x1,x2
// split-KV partials
#define PBUF ((size_t)B * N1 * INNER)
#define MBUF (B * HEADS * N1)
__device__ __half g_aop[NSPLIT * PBUF];           // unnormalized O partials
__device__ float2 g_ml [NSPLIT * MBUF];           // per-row (m, l), log2 domain

// ---------------------------------------------------------------------------
// PTX helpers (baseline sm_80-level only — safe for compute_103 target)
// ---------------------------------------------------------------------------
__device__ __forceinline__ uint32_t smem_u32(const void* p) {
    uint32_t a;
    asm("{ .reg .u64 t; cvta.to.shared.u64 t, %1; cvt.u32.u64 %0, t; }"
        : "=r"(a) : "l"(p));
    return a;
}
__device__ __forceinline__ void cpasync16(uint32_t dst, const void* src) {
    asm volatile("cp.async.cg.shared.global [%0], [%1], 16;"
                 :: "r"(dst), "l"(src) : "memory");
}
#define CP_COMMIT() asm volatile("cp.async.commit_group;" ::: "memory")
#define CP_WAIT0()  asm volatile("cp.async.wait_group 0;" ::: "memory")
#define CP_WAIT2()  asm volatile("cp.async.wait_group 2;" ::: "memory")

// f16 mma m16n8k16, f32 accumulate. A row-major (16x16), B col-major (16x8).
__device__ __forceinline__ void mma_f16(float* d, const uint32_t* a, const uint32_t* b) {
    asm volatile(
        "mma.sync.aligned.m16n8k16.row.col.f32.f16.f16.f32 "
        "{%0,%1,%2,%3}, {%4,%5,%6,%7}, {%8,%9}, {%0,%1,%2,%3};"
        : "+f"(d[0]), "+f"(d[1]), "+f"(d[2]), "+f"(d[3])
        : "r"(a[0]), "r"(a[1]), "r"(a[2]), "r"(a[3]), "r"(b[0]), "r"(b[1]));
}

__device__ __forceinline__ void ldmatrix_x4(
    uint32_t& r0, uint32_t& r1, uint32_t& r2, uint32_t& r3, uint32_t addr)
{
    asm volatile("ldmatrix.sync.aligned.m8n8.x4.shared.b16 {%0,%1,%2,%3}, [%4];"
                 : "=r"(r0), "=r"(r1), "=r"(r2), "=r"(r3) : "r"(addr));
}
__device__ __forceinline__ void ldmatrix_x4_trans(
    uint32_t& r0, uint32_t& r1, uint32_t& r2, uint32_t& r3, uint32_t addr)
{
    asm volatile("ldmatrix.sync.aligned.m8n8.x4.trans.shared.b16 {%0,%1,%2,%3}, [%4];"
                 : "=r"(r0), "=r"(r1), "=r"(r2), "=r"(r3) : "r"(addr));
}

__device__ __forceinline__ uint32_t packh2(float x, float y) {
    __half2 h = __floats2half2_rn(x, y);
    return *reinterpret_cast<uint32_t*>(&h);
}
__device__ __forceinline__ uint32_t ldh2(const __half* p) {
    return *reinterpret_cast<const uint32_t*>(p);
}

// ---------------------------------------------------------------------------
// Streaming f32 -> f16 convert for the 6 weights (NO transpose; native [K,N]).
// ---------------------------------------------------------------------------
__global__ void conv_w(const float* __restrict__ Wq1, const float* __restrict__ Wk1,
                       const float* __restrict__ Wv1, const float* __restrict__ Wk2,
                       const float* __restrict__ Wv2, const float* __restrict__ Wo,
                       __half* __restrict__ wt)
{
    const int z = blockIdx.z;
    const float* src = (z == 0) ? Wq1 : (z == 1) ? Wk1 : (z == 2) ? Wv1
                     : (z == 3) ? Wk2 : (z == 4) ? Wv2 : Wo;
    __half* dst = wt + (size_t)z * WSZ;
    const size_t n4 = WSZ / 4;
    for (size_t i = (size_t)blockIdx.x * blockDim.x + threadIdx.x;
         i < n4; i += (size_t)gridDim.x * blockDim.x) {
        const float4 v = ((const float4*)src)[i];
        uint2 o;
        o.x = packh2(v.x, v.y);
        o.y = packh2(v.z, v.w);
        ((uint2*)dst)[i] = o;
    }
}

// ---------------------------------------------------------------------------
// Convert x1, x2 to f16 into g_xr
// ---------------------------------------------------------------------------
#define XF4 ((size_t)MTOT * D / 4)
__global__ void conv_x(const float* __restrict__ x1, const float* __restrict__ x2,
                       __half* __restrict__ xr)
{
    const size_t total = 2 * XF4;
    for (size_t i = (size_t)blockIdx.x * blockDim.x + threadIdx.x;
         i < total; i += (size_t)gridDim.x * blockDim.x) {
        const float4 v = (i < XF4) ? ((const float4*)x1)[i] : ((const float4*)x2)[i - XF4];
        uint2 o;
        o.x = packh2(v.x, v.y);
        o.y = packh2(v.z, v.w);
        ((uint2*)xr)[i] = o;
    }
}

// ---------------------------------------------------------------------------
// cp.async double-buffered f16 GEMM core (128x128, BK=32, 8 warps)  [R12]
// A-frags via ldmatrix.x4 (pitch KP=40); B-frags via ldmatrix.x4.trans from
// a [32 k][128 n] tile (pitch NPITCH=136).
// ---------------------------------------------------------------------------
#define KP 40
#define ABUF_H (128 * KP)               // 5120 halves
#define NPITCH 136
#define BBUF_H (32 * NPITCH)            // 4352 halves
#define GSTG_H (ABUF_H + BBUF_H)        // stage halves (9472)

__device__ __forceinline__ void gemm_core(
    const __half* __restrict__ A, const __half* __restrict__ W,
    void* __restrict__ C, const float* __restrict__ bias,
    int K, int N, size_t cstride, size_t coff, float scale, bool outHalf)
{
    extern __shared__ __half gsm[];

    const int tid = threadIdx.x;
    const int w = tid >> 5, lane = tid & 31;
    const int g = lane >> 2, tg = lane & 3;
    const int wm = (w & 1) * 64, wn = (w >> 1) * 32;
    const int m0 = blockIdx.y * 128, n0 = blockIdx.x * 128;

    const int lr = tid >> 1;
    const int lc = (tid & 1) * 16;
    const int br = tid >> 3;
    const int bc = (tid & 7) * 16;

    const __half* Ag = A + (size_t)(m0 + lr) * K + lc;
    const __half* Bg = W + (size_t)br * N + n0 + bc;

    const uint32_t smb  = smem_u32(gsm);
    const uint32_t offA = (uint32_t)(lr * KP + lc) * 2;
    const uint32_t offB = (uint32_t)(ABUF_H + br * NPITCH + bc) * 2;

    const int sub = lane >> 3, rw = lane & 7;
    const int a_roff = (sub & 1) * 8, a_koff = (sub >> 1) * 8;
    const int t_vr  = (sub & 1) * 8 + rw;
    const int t_vcb = (sub >> 1) * 8;

    #pragma unroll
    for (int c = 0; c < 2; c++) {
        cpasync16(smb + offA + 16 * c, Ag + 8 * c);
        cpasync16(smb + offB + 16 * c, Bg + 8 * c);
    }
    CP_COMMIT();

    float acc[4][4][4] = {};
    const int S = K >> 5;
    for (int s = 0; s < S; s++) {
        CP_WAIT0();
        __syncthreads();
        if (s + 1 < S) {
            const uint32_t sb = smb + (uint32_t)(((s + 1) & 1) * GSTG_H) * 2;
            const __half* Ag2 = Ag + (size_t)(s + 1) * 32;
            const __half* Bg2 = Bg + (size_t)(s + 1) * 32 * N;
            #pragma unroll
            for (int c = 0; c < 2; c++) {
                cpasync16(sb + offA + 16 * c, Ag2 + 8 * c);
                cpasync16(sb + offB + 16 * c, Bg2 + 8 * c);
            }
            CP_COMMIT();
        }
        const uint32_t asb = smb + (uint32_t)((s & 1) * GSTG_H) * 2;
        const uint32_t bsb = asb + ABUF_H * 2;

        #pragma unroll
        for (int ks = 0; ks < 2; ks++) {
            const int k0 = 16 * ks;
            uint32_t af[4][4], bf[4][2];
            #pragma unroll
            for (int mt = 0; mt < 4; mt++) {
                const uint32_t aa = asb +
                    (uint32_t)((wm + 16 * mt + a_roff + rw) * KP + k0 + a_koff) * 2;
                ldmatrix_x4(af[mt][0], af[mt][1], af[mt][2], af[mt][3], aa);
            }
            #pragma unroll
            for (int np = 0; np < 2; np++) {
                const uint32_t ba = bsb +
                    (uint32_t)((k0 + t_vr) * NPITCH + wn + 16 * np + t_vcb) * 2;
                ldmatrix_x4_trans(bf[2 * np][0], bf[2 * np][1],
                                  bf[2 * np + 1][0], bf[2 * np + 1][1], ba);
            }
            #pragma unroll
            for (int mt = 0; mt < 4; mt++)
                #pragma unroll
                for (int nt = 0; nt < 4; nt++)
                    mma_f16(acc[mt][nt], af[mt], bf[nt]);
        }
    }

    #pragma unroll
    for (int mt = 0; mt < 4; mt++) {
        const size_t r0 = (size_t)(m0 + wm + 16 * mt + g);
        const size_t r1 = r0 + 8;
        const size_t o0 = (r0 >> 11) * cstride + (r0 & 2047) * N + coff;
        const size_t o1 = (r1 >> 11) * cstride + (r1 & 2047) * N + coff;
        #pragma unroll
        for (int nt = 0; nt < 4; nt++) {
            const int cc = n0 + wn + 8 * nt + 2 * tg;
            float v00 = acc[mt][nt][0] * scale;
            float v01 = acc[mt][nt][1] * scale;
            float v10 = acc[mt][nt][2] * scale;
            float v11 = acc[mt][nt][3] * scale;
            if (outHalf) {
                *(uint32_t*)((__half*)C + o0 + cc) = packh2(v00, v01);
                *(uint32_t*)((__half*)C + o1 + cc) = packh2(v10, v11);
            } else {
                const float bx = bias ? bias[cc] : 0.f;
                const float by = bias ? bias[cc + 1] : 0.f;
                *(float2*)((float*)C + o0 + cc) = make_float2(v00 + bx, v01 + by);
                *(float2*)((float*)C + o1 + cc) = make_float2(v10 + bx, v11 + by);
            }
        }
    }
}

__global__ __launch_bounds__(256, 2)
void gemm5(const __half* __restrict__ x1r, const __half* __restrict__ x2r,
           const __half* __restrict__ wt,
           __half* __restrict__ q1, __half* __restrict__ k, __half* __restrict__ v)
{
    const int z = blockIdx.z;
    const __half* A = (z < 3) ? x1r : x2r;
    const __half* W = wt + (size_t)z * WSZ;
    const size_t kvs  = (size_t)NKV * INNER;
    const size_t off2 = (size_t)N1 * INNER;
    __half* Cp; size_t cs, co; float sc;
    if (z == 0)      { Cp = q1; cs = (size_t)N1 * INNER; co = 0;    sc = SCALE_Q; }
    else if (z == 1) { Cp = k;  cs = kvs;                co = 0;    sc = 1.f; }
    else if (z == 2) { Cp = v;  cs = kvs;                co = 0;    sc = 1.f; }
    else if (z == 3) { Cp = k;  cs = kvs;                co = off2; sc = 1.f; }
    else             { Cp = v;  cs = kvs;                co = off2; sc = 1.f; }
    gemm_core(A, W, Cp, nullptr, D, INNER, cs, co, sc, true);
}

__global__ __launch_bounds__(256, 2)
void gemmO(const __half* __restrict__ ao, const __half* __restrict__ wt5,
           float* __restrict__ out, const float* __restrict__ bo)
{
    gemm_core(ao, wt5, out, bo, INNER, D, (size_t)N1 * D, 0, 1.f, false);
}

// ---------------------------------------------------------------------------
// Flash attention v9: split-KV x4, 4-stage ring, 1 barrier / 2 tiles,
// LAZY (deferred) max + MMA-based row sums.
// ---------------------------------------------------------------------------
#define APH 72
#define KV_H   (64 * APH)           // halves per K (or V) tile
#define FBUF_H (2 * KV_H)           // halves per stage (K+V)

__global__ __launch_bounds__(256, 2)
void flash9(const __half* __restrict__ q, const __half* __restrict__ kc,
            const __half* __restrict__ vc,
            __half* __restrict__ aop, float2* __restrict__ ml)
{
    extern __shared__ __half fsm[];

    const int z  = blockIdx.z;
    const int b  = z >> 2;            // NSPLIT == 4
    const int sp = z & 3;
    const int h  = blockIdx.y;
    const int qt = blockIdx.x;
    const int tid  = threadIdx.x;
    const int w = tid >> 5, lane = tid & 31;
    const int g = lane >> 2, tg = lane & 3;
    const int m0 = 16 * w;

    const __half* qb = q  + ((size_t)b * N1 + (size_t)qt * 128) * INNER + h * DHEAD;
    const __half* kb = kc + ((size_t)b * NKV + (size_t)sp * KVS) * INNER + h * DHEAD;
    const __half* vb = vc + ((size_t)b * NKV + (size_t)sp * KVS) * INNER + h * DHEAD;

    const uint32_t smb = smem_u32(fsm);

    const int cr = tid >> 2;
    const int cc0 = (tid & 3) * 16;
    const uint32_t rowK = (uint32_t)(cr * APH + cc0) * 2;
    const uint32_t rowV = rowK + KV_H * 2;

    // --- preload KV tiles 0,1 into stages 0,1 ---
    #pragma unroll
    for (int s = 0; s < 2; s++) {
        const uint32_t sb = smb + (uint32_t)(s * FBUF_H) * 2;
        const __half* ks = kb + (size_t)s * 64 * INNER + (size_t)cr * INNER + cc0;
        const __half* vs = vb + (size_t)s * 64 * INNER + (size_t)cr * INNER + cc0;
        #pragma unroll
        for (int c = 0; c < 2; c++) {
            cpasync16(sb + rowK + 16 * c, ks + 8 * c);
            cpasync16(sb + rowV + 16 * c, vs + 8 * c);
        }
        CP_COMMIT();
    }

    // --- Q A-fragments from gmem ---
    uint32_t qaf[4][4];
    {
        const __half* q0 = qb + (size_t)(m0 + g) * INNER;
        const __half* q1r = q0 + 8 * INNER;
        #pragma unroll
        for (int s = 0; s < 4; s++) {
            qaf[s][0] = ldh2(q0  + 16 * s + 2 * tg);
            qaf[s][1] = ldh2(q1r + 16 * s + 2 * tg);
            qaf[s][2] = ldh2(q0  + 16 * s + 2 * tg + 8);
            qaf[s][3] = ldh2(q1r + 16 * s + 2 * tg + 8);
        }
    }

    float accO[8][4] = {};
    float mrun0 = 0.f, mrun1 = 0.f, lrun0 = 0.f, lrun1 = 0.f;

    const int sub = lane >> 3, rw = lane & 7;
    const int k_roff = (sub >> 1) * 8, k_koff = (sub & 1) * 8;
    const int vr = (sub & 1) * 8 + rw;
    const int vcb = (sub >> 1) * 8;

    const uint32_t bones[2] = { 0x3C003C00u, 0x3C003C00u };   // f16 ones B-frag

    const int NT = KVS / 64;     // 16
    for (int r = 0; r < NT / 2; r++) {
        __syncthreads();   // all warps done with tiles 2r-2, 2r-1 (stage reuse)

        const int jp0 = 2 * r + 2;
        if (jp0 < NT) {
            #pragma unroll
            for (int t = 0; t < 2; t++) {
                const int jp = jp0 + t;
                const uint32_t sb = smb + (uint32_t)((jp & 3) * FBUF_H) * 2;
                const __half* ks = kb + (size_t)jp * 64 * INNER + (size_t)cr * INNER + cc0;
                const __half* vs = vb + (size_t)jp * 64 * INNER + (size_t)cr * INNER + cc0;
                #pragma unroll
                for (int c = 0; c < 2; c++) {
                    cpasync16(sb + rowK + 16 * c, ks + 8 * c);
                    cpasync16(sb + rowV + 16 * c, vs + 8 * c);
                }
                CP_COMMIT();
            }
            CP_WAIT2();
        } else {
            CP_WAIT0();
        }

        #pragma unroll
        for (int t = 0; t < 2; t++) {
            const int j = 2 * r + t;
            const uint32_t ksb = smb + (uint32_t)((j & 3) * FBUF_H) * 2;
            const uint32_t vsb = ksb + KV_H * 2;

            // --- S = Q @ K^T ---
            float sacc[8][4] = {};
            #pragma unroll
            for (int ks = 0; ks < 4; ks++) {
                const int k0 = 16 * ks;
                #pragma unroll
                for (int np = 0; np < 4; np++) {
                    uint32_t b0, b1, b2, b3;
                    const uint32_t ka = ksb +
                        (uint32_t)((16 * np + k_roff + rw) * APH + k0 + k_koff) * 2;
                    ldmatrix_x4(b0, b1, b2, b3, ka);
                    uint32_t bf0[2] = { b0, b1 };
                    uint32_t bf1[2] = { b2, b3 };
                    mma_f16(sacc[2 * np],     qaf[ks], bf0);
                    mma_f16(sacc[2 * np + 1], qaf[ks], bf1);
                }
            }

            // --- tile 0: establish proper initial max before first exp ---
            if (j == 0) {
                float im0 = -1e30f, im1 = -1e30f;
                #pragma unroll
                for (int nt = 0; nt < 8; nt++) {
                    im0 = fmaxf(im0, fmaxf(sacc[nt][0], sacc[nt][1]));
                    im1 = fmaxf(im1, fmaxf(sacc[nt][2], sacc[nt][3]));
                }
                #pragma unroll
                for (int off = 1; off <= 2; off <<= 1) {
                    im0 = fmaxf(im0, __shfl_xor_sync(0xFFFFFFFFu, im0, off));
                    im1 = fmaxf(im1, __shfl_xor_sync(0xFFFFFFFFu, im1, off));
                }
                mrun0 = im0;
                mrun1 = im1;
            }

            // --- exp with (stale) running max: starts immediately ---
            uint32_t paf[4][4];
            #pragma unroll
            for (int ks = 0; ks < 4; ks++) {
                const int e0 = 2 * ks, e1 = 2 * ks + 1;
                float p00 = exp2f(sacc[e0][0] - mrun0);
                float p01 = exp2f(sacc[e0][1] - mrun0);
                float p10 = exp2f(sacc[e0][2] - mrun1);
                float p11 = exp2f(sacc[e0][3] - mrun1);
                float p20 = exp2f(sacc[e1][0] - mrun0);
                float p21 = exp2f(sacc[e1][1] - mrun0);
                float p30 = exp2f(sacc[e1][2] - mrun1);
                float p31 = exp2f(sacc[e1][3] - mrun1);
                paf[ks][0] = packh2(p00, p01);
                paf[ks][1] = packh2(p10, p11);
                paf[ks][2] = packh2(p20, p21);
                paf[ks][3] = packh2(p30, p31);
            }

            // --- trailing max reduce (off the exp critical path) ---
            float rm0 = -1e30f, rm1 = -1e30f;
            #pragma unroll
            for (int nt = 0; nt < 8; nt++) {
                rm0 = fmaxf(rm0, fmaxf(sacc[nt][0], sacc[nt][1]));
                rm1 = fmaxf(rm1, fmaxf(sacc[nt][2], sacc[nt][3]));
            }
            #pragma unroll
            for (int off = 1; off <= 2; off <<= 1) {
                rm0 = fmaxf(rm0, __shfl_xor_sync(0xFFFFFFFFu, rm0, off));
                rm1 = fmaxf(rm1, __shfl_xor_sync(0xFFFFFFFFu, rm1, off));
            }

            // --- row sums via MMA with ones (every lane gets its row's sum) ---
            float sumacc[4] = { 0.f, 0.f, 0.f, 0.f };
            #pragma unroll
            for (int ks = 0; ks < 4; ks++)
                mma_f16(sumacc, paf[ks], bones);

            // --- O += P @ V ---
            #pragma unroll
            for (int ks = 0; ks < 4; ks++) {
                #pragma unroll
                for (int dp = 0; dp < 4; dp++) {
                    uint32_t r0, r1, r2, r3;
                    const uint32_t addr = vsb +
                        (uint32_t)((16 * ks + vr) * APH + 16 * dp + vcb) * 2;
                    ldmatrix_x4_trans(r0, r1, r2, r3, addr);
                    uint32_t bf0[2] = { r0, r1 };
                    uint32_t bf1[2] = { r2, r3 };
                    mma_f16(accO[2 * dp],     paf[ks], bf0);
                    mma_f16(accO[2 * dp + 1], paf[ks], bf1);
                }
            }

            lrun0 += sumacc[0];
            lrun1 += sumacc[2];

            // --- deferred rescale (rare): bring state into new-max units ---
            const float mn0 = fmaxf(mrun0, rm0);
            const float mn1 = fmaxf(mrun1, rm1);
            const float al0 = exp2f(mrun0 - mn0);
            const float al1 = exp2f(mrun1 - mn1);
            if (!__all_sync(0xFFFFFFFFu, (al0 == 1.f) && (al1 == 1.f))) {
                #pragma unroll
                for (int nt = 0; nt < 8; nt++) {
                    accO[nt][0] *= al0; accO[nt][1] *= al0;
                    accO[nt][2] *= al1; accO[nt][3] *= al1;
                }
                lrun0 *= al0;
                lrun1 *= al1;
            }
            mrun0 = mn0;
            mrun1 = mn1;
        }
    }

    // --- write UNNORMALIZED partial O (f16) + (m,l) per row ---
    {
        const int qr0 = qt * 128 + m0 + g;
        __half* d0 = aop + (size_t)sp * PBUF
                   + ((size_t)b * N1 + qr0) * INNER + h * DHEAD;
        __half* d1 = d0 + 8 * INNER;
        #pragma unroll
        for (int nt = 0; nt < 8; nt++) {
            const int cc = 8 * nt + 2 * tg;
            *(uint32_t*)(d0 + cc) = packh2(accO[nt][0], accO[nt][1]);
            *(uint32_t*)(d1 + cc) = packh2(accO[nt][2], accO[nt][3]);
        }
        if (tg == 0) {
            float2* mlp = ml + (size_t)sp * MBUF
                        + ((size_t)b * HEADS + h) * N1;
            mlp[qr0]     = make_float2(mrun0, lrun0);
            mlp[qr0 + 8] = make_float2(mrun1, lrun1);
        }
    }
}

// ---------------------------------------------------------------------------
// Combine NSPLIT partials (unchanged).
// ---------------------------------------------------------------------------
__global__ __launch_bounds__(256)
void combine4(const __half* __restrict__ aop, const float2* __restrict__ ml,
              __half* __restrict__ ao)
{
    const int bid = blockIdx.x;
    const int b   = bid >> 11;           // N1 == 2048
    const int row = bid & 2047;
    const int t   = threadIdx.x;
    const int h   = t >> 5;
    const int d   = (t & 31) * 2;

    const size_t mlIdx = ((size_t)b * HEADS + h) * N1 + row;
    float2 m0 = ml[0 * MBUF + mlIdx];
    float2 m1 = ml[1 * MBUF + mlIdx];
    float2 m2 = ml[2 * MBUF + mlIdx];
    float2 m3 = ml[3 * MBUF + mlIdx];

    const float mm = fmaxf(fmaxf(m0.x, m1.x), fmaxf(m2.x, m3.x));
    const float w0 = exp2f(m0.x - mm);
    const float w1 = exp2f(m1.x - mm);
    const float w2 = exp2f(m2.x - mm);
    const float w3 = exp2f(m3.x - mm);
    const float inv = 1.0f / (w0 * m0.y + w1 * m1.y + w2 * m2.y + w3 * m3.y);

    const size_t ofs = ((size_t)b * N1 + row) * INNER + h * DHEAD + d;
    const __half2 o0 = *(const __half2*)(aop + 0 * PBUF + ofs);
    const __half2 o1 = *(const __half2*)(aop + 1 * PBUF + ofs);
    const __half2 o2 = *(const __half2*)(aop + 2 * PBUF + ofs);
    const __half2 o3 = *(const __half2*)(aop + 3 * PBUF + ofs);

    const float2 f0 = __half22float2(o0);
    const float2 f1 = __half22float2(o1);
    const float2 f2 = __half22float2(o2);
    const float2 f3 = __half22float2(o3);

    const float ox = (w0 * f0.x + w1 * f1.x + w2 * f2.x + w3 * f3.x) * inv;
    const float oy = (w0 * f0.y + w1 * f1.y + w2 * f2.y + w3 * f3.y) * inv;
    *(uint32_t*)(ao + ofs) = packh2(ox, oy);
}

// ---------------------------------------------------------------------------
// Launch
// ---------------------------------------------------------------------------
extern "C" void kernel_launch(void* const* d_in, const int* in_sizes, int n_in,
                              void* d_out, int out_size)
{
    (void)in_sizes; (void)n_in; (void)out_size;

    const float* x1  = (const float*)d_in[0];
    const float* x2  = (const float*)d_in[1];
    const float* Wq1 = (const float*)d_in[2];
    const float* Wk1 = (const float*)d_in[3];
    const float* Wv1 = (const float*)d_in[4];
    const float* Wk2 = (const float*)d_in[5];
    const float* Wv2 = (const float*)d_in[6];
    const float* Wo  = (const float*)d_in[7];
    const float* bo  = (const float*)d_in[8];
    float* out = (float*)d_out;

    __half *q1, *kbuf, *vbuf, *aobuf, *wt, *xr, *aop;
    float2* mlb;
    cudaGetSymbolAddress((void**)&q1,    g_q1);
    cudaGetSymbolAddress((void**)&kbuf,  g_k);
    cudaGetSymbolAddress((void**)&vbuf,  g_v);
    cudaGetSymbolAddress((void**)&aobuf, g_ao);
    cudaGetSymbolAddress((void**)&wt,    g_wt);
    cudaGetSymbolAddress((void**)&xr,    g_xr);
    cudaGetSymbolAddress((void**)&aop,   g_aop);
    cudaGetSymbolAddress((void**)&mlb,   g_ml);

    const int gemm_smem  = 2 * GSTG_H * (int)sizeof(__half);  // 37888
    const int flash_smem = 4 * FBUF_H * (int)sizeof(__half);  // 73728
    cudaFuncSetAttribute(gemm5,  cudaFuncAttributeMaxDynamicSharedMemorySize, gemm_smem);
    cudaFuncSetAttribute(gemmO,  cudaFuncAttributeMaxDynamicSharedMemorySize, gemm_smem);
    cudaFuncSetAttribute(flash9, cudaFuncAttributeMaxDynamicSharedMemorySize, flash_smem);

    conv_w<<<dim3(128, 1, 6), 256>>>(Wq1, Wk1, Wv1, Wk2, Wv2, Wo, wt);
    conv_x<<<4096, 256>>>(x1, x2, xr);

    gemm5<<<dim3(INNER / 128, MTOT / 128, 5), 256, gemm_smem>>>(
        xr, xr + (size_t)MTOT * D, wt, q1, kbuf, vbuf);

    flash9<<<dim3(N1 / 128, HEADS, B * NSPLIT), 256, flash_smem>>>(
        q1, kbuf, vbuf, aop, mlb);

    combine4<<<B * N1, 256>>>(aop, mlb, aobuf);

    gemmO<<<dim3(D / 128, MTOT / 128, 1), 256, gemm_smem>>>(aobuf, wt + 5 * WSZ, out, bo);
}

// round 16
// speedup vs baseline: 1.2074x; 1.0196x over previous
#include <cuda_runtime.h>
#include <cuda_fp16.h>
#include <cstddef>
#include <cstdint>

// ---------------------------------------------------------------------------
// Problem constants
// ---------------------------------------------------------------------------
#define B     4
#define N1    2048
#define N2    2048
#define D     1024
#define HEADS 8
#define DHEAD 64
#define INNER (HEADS * DHEAD)     // 512
#define NKV   (N1 + N2)           // 4096
#define MTOT  (B * N1)            // 8192
#define NSPLIT 4
#define KVS   (NKV / NSPLIT)      // 1024 keys per split

#define SCALE_Q 0.18033688011112042f   // 0.125 * log2(e)

// Scratch (device globals — no allocation allowed), all fp16
__device__ __half g_q1[(size_t)B * N1 * INNER];
__device__ __half g_k [(size_t)B * NKV * INNER];
__device__ __half g_v [(size_t)B * NKV * INNER];
__device__ __half g_ao[(size_t)B * N1 * INNER];
#define WSZ (1024 * 512)
__device__ __half g_wt[6 * WSZ];                  // f16 weights, NATIVE [K,N]
__device__ __half g_xr[2 * (size_t)MTOT * D];     // converted x1,x2
// split-KV partials
#define PBUF ((size_t)B * N1 * INNER)
#define MBUF (B * HEADS * N1)
__device__ __half g_aop[NSPLIT * PBUF];           // unnormalized O partials
__device__ float2 g_ml [NSPLIT * MBUF];           // per-row (m, l), log2 domain

// ---------------------------------------------------------------------------
// PTX helpers (baseline sm_80-level only — safe for compute_103 target)
// ---------------------------------------------------------------------------
__device__ __forceinline__ uint32_t smem_u32(const void* p) {
    uint32_t a;
    asm("{ .reg .u64 t; cvta.to.shared.u64 t, %1; cvt.u32.u64 %0, t; }"
        : "=r"(a) : "l"(p));
    return a;
}
__device__ __forceinline__ void cpasync16(uint32_t dst, const void* src) {
    asm volatile("cp.async.cg.shared.global [%0], [%1], 16;"
                 :: "r"(dst), "l"(src) : "memory");
}
#define CP_COMMIT() asm volatile("cp.async.commit_group;" ::: "memory")
#define CP_WAIT0()  asm volatile("cp.async.wait_group 0;" ::: "memory")
#define CP_WAIT2()  asm volatile("cp.async.wait_group 2;" ::: "memory")

// f16 mma m16n8k16, f32 accumulate. A row-major (16x16), B col-major (16x8).
__device__ __forceinline__ void mma_f16(float* d, const uint32_t* a, const uint32_t* b) {
    asm volatile(
        "mma.sync.aligned.m16n8k16.row.col.f32.f16.f16.f32 "
        "{%0,%1,%2,%3}, {%4,%5,%6,%7}, {%8,%9}, {%0,%1,%2,%3};"
        : "+f"(d[0]), "+f"(d[1]), "+f"(d[2]), "+f"(d[3])
        : "r"(a[0]), "r"(a[1]), "r"(a[2]), "r"(a[3]), "r"(b[0]), "r"(b[1]));
}

__device__ __forceinline__ void ldmatrix_x4(
    uint32_t& r0, uint32_t& r1, uint32_t& r2, uint32_t& r3, uint32_t addr)
{
    asm volatile("ldmatrix.sync.aligned.m8n8.x4.shared.b16 {%0,%1,%2,%3}, [%4];"
                 : "=r"(r0), "=r"(r1), "=r"(r2), "=r"(r3) : "r"(addr));
}
__device__ __forceinline__ void ldmatrix_x4_trans(
    uint32_t& r0, uint32_t& r1, uint32_t& r2, uint32_t& r3, uint32_t addr)
{
    asm volatile("ldmatrix.sync.aligned.m8n8.x4.trans.shared.b16 {%0,%1,%2,%3}, [%4];"
                 : "=r"(r0), "=r"(r1), "=r"(r2), "=r"(r3) : "r"(addr));
}

__device__ __forceinline__ uint32_t packh2(float x, float y) {
    __half2 h = __floats2half2_rn(x, y);
    return *reinterpret_cast<uint32_t*>(&h);
}
__device__ __forceinline__ uint32_t ldh2(const __half* p) {
    return *reinterpret_cast<const uint32_t*>(p);
}
// packed f16x2 exp2 (single MUFU op for two values)
__device__ __forceinline__ uint32_t h2ex2(uint32_t x) {
    uint32_t r;
    asm("ex2.approx.f16x2 %0, %1;" : "=r"(r) : "r"(x));
    return r;
}

// ---------------------------------------------------------------------------
// Streaming f32 -> f16 convert for the 6 weights (NO transpose; native [K,N]).
// ---------------------------------------------------------------------------
__global__ void conv_w(const float* __restrict__ Wq1, const float* __restrict__ Wk1,
                       const float* __restrict__ Wv1, const float* __restrict__ Wk2,
                       const float* __restrict__ Wv2, const float* __restrict__ Wo,
                       __half* __restrict__ wt)
{
    const int z = blockIdx.z;
    const float* src = (z == 0) ? Wq1 : (z == 1) ? Wk1 : (z == 2) ? Wv1
                     : (z == 3) ? Wk2 : (z == 4) ? Wv2 : Wo;
    __half* dst = wt + (size_t)z * WSZ;
    const size_t n4 = WSZ / 4;
    for (size_t i = (size_t)blockIdx.x * blockDim.x + threadIdx.x;
         i < n4; i += (size_t)gridDim.x * blockDim.x) {
        const float4 v = ((const float4*)src)[i];
        uint2 o;
        o.x = packh2(v.x, v.y);
        o.y = packh2(v.z, v.w);
        ((uint2*)dst)[i] = o;
    }
}

// ---------------------------------------------------------------------------
// Convert x1, x2 to f16 into g_xr
// ---------------------------------------------------------------------------
#define XF4 ((size_t)MTOT * D / 4)
__global__ void conv_x(const float* __restrict__ x1, const float* __restrict__ x2,
                       __half* __restrict__ xr)
{
    const size_t total = 2 * XF4;
    for (size_t i = (size_t)blockIdx.x * blockDim.x + threadIdx.x;
         i < total; i += (size_t)gridDim.x * blockDim.x) {
        const float4 v = (i < XF4) ? ((const float4*)x1)[i] : ((const float4*)x2)[i - XF4];
        uint2 o;
        o.x = packh2(v.x, v.y);
        o.y = packh2(v.z, v.w);
        ((uint2*)xr)[i] = o;
    }
}

// ---------------------------------------------------------------------------
// cp.async double-buffered f16 GEMM core (128x128, BK=32, 8 warps)  [R12]
// A-frags via ldmatrix.x4 (pitch KP=40); B-frags via ldmatrix.x4.trans from
// a [32 k][128 n] tile (pitch NPITCH=136).
// ---------------------------------------------------------------------------
#define KP 40
#define ABUF_H (128 * KP)               // 5120 halves
#define NPITCH 136
#define BBUF_H (32 * NPITCH)            // 4352 halves
#define GSTG_H (ABUF_H + BBUF_H)        // stage halves (9472)

__device__ __forceinline__ void gemm_core(
    const __half* __restrict__ A, const __half* __restrict__ W,
    void* __restrict__ C, const float* __restrict__ bias,
    int K, int N, size_t cstride, size_t coff, float scale, bool outHalf)
{
    extern __shared__ __half gsm[];

    const int tid = threadIdx.x;
    const int w = tid >> 5, lane = tid & 31;
    const int g = lane >> 2, tg = lane & 3;
    const int wm = (w & 1) * 64, wn = (w >> 1) * 32;
    const int m0 = blockIdx.y * 128, n0 = blockIdx.x * 128;

    const int lr = tid >> 1;
    const int lc = (tid & 1) * 16;
    const int br = tid >> 3;
    const int bc = (tid & 7) * 16;

    const __half* Ag = A + (size_t)(m0 + lr) * K + lc;
    const __half* Bg = W + (size_t)br * N + n0 + bc;

    const uint32_t smb  = smem_u32(gsm);
    const uint32_t offA = (uint32_t)(lr * KP + lc) * 2;
    const uint32_t offB = (uint32_t)(ABUF_H + br * NPITCH + bc) * 2;

    const int sub = lane >> 3, rw = lane & 7;
    const int a_roff = (sub & 1) * 8, a_koff = (sub >> 1) * 8;
    const int t_vr  = (sub & 1) * 8 + rw;
    const int t_vcb = (sub >> 1) * 8;

    #pragma unroll
    for (int c = 0; c < 2; c++) {
        cpasync16(smb + offA + 16 * c, Ag + 8 * c);
        cpasync16(smb + offB + 16 * c, Bg + 8 * c);
    }
    CP_COMMIT();

    float acc[4][4][4] = {};
    const int S = K >> 5;
    for (int s = 0; s < S; s++) {
        CP_WAIT0();
        __syncthreads();
        if (s + 1 < S) {
            const uint32_t sb = smb + (uint32_t)(((s + 1) & 1) * GSTG_H) * 2;
            const __half* Ag2 = Ag + (size_t)(s + 1) * 32;
            const __half* Bg2 = Bg + (size_t)(s + 1) * 32 * N;
            #pragma unroll
            for (int c = 0; c < 2; c++) {
                cpasync16(sb + offA + 16 * c, Ag2 + 8 * c);
                cpasync16(sb + offB + 16 * c, Bg2 + 8 * c);
            }
            CP_COMMIT();
        }
        const uint32_t asb = smb + (uint32_t)((s & 1) * GSTG_H) * 2;
        const uint32_t bsb = asb + ABUF_H * 2;

        #pragma unroll
        for (int ks = 0; ks < 2; ks++) {
            const int k0 = 16 * ks;
            uint32_t af[4][4], bf[4][2];
            #pragma unroll
            for (int mt = 0; mt < 4; mt++) {
                const uint32_t aa = asb +
                    (uint32_t)((wm + 16 * mt + a_roff + rw) * KP + k0 + a_koff) * 2;
                ldmatrix_x4(af[mt][0], af[mt][1], af[mt][2], af[mt][3], aa);
            }
            #pragma unroll
            for (int np = 0; np < 2; np++) {
                const uint32_t ba = bsb +
                    (uint32_t)((k0 + t_vr) * NPITCH + wn + 16 * np + t_vcb) * 2;
                ldmatrix_x4_trans(bf[2 * np][0], bf[2 * np][1],
                                  bf[2 * np + 1][0], bf[2 * np + 1][1], ba);
            }
            #pragma unroll
            for (int mt = 0; mt < 4; mt++)
                #pragma unroll
                for (int nt = 0; nt < 4; nt++)
                    mma_f16(acc[mt][nt], af[mt], bf[nt]);
        }
    }

    #pragma unroll
    for (int mt = 0; mt < 4; mt++) {
        const size_t r0 = (size_t)(m0 + wm + 16 * mt + g);
        const size_t r1 = r0 + 8;
        const size_t o0 = (r0 >> 11) * cstride + (r0 & 2047) * N + coff;
        const size_t o1 = (r1 >> 11) * cstride + (r1 & 2047) * N + coff;
        #pragma unroll
        for (int nt = 0; nt < 4; nt++) {
            const int cc = n0 + wn + 8 * nt + 2 * tg;
            float v00 = acc[mt][nt][0] * scale;
            float v01 = acc[mt][nt][1] * scale;
            float v10 = acc[mt][nt][2] * scale;
            float v11 = acc[mt][nt][3] * scale;
            if (outHalf) {
                *(uint32_t*)((__half*)C + o0 + cc) = packh2(v00, v01);
                *(uint32_t*)((__half*)C + o1 + cc) = packh2(v10, v11);
            } else {
                const float bx = bias ? bias[cc] : 0.f;
                const float by = bias ? bias[cc + 1] : 0.f;
                *(float2*)((float*)C + o0 + cc) = make_float2(v00 + bx, v01 + by);
                *(float2*)((float*)C + o1 + cc) = make_float2(v10 + bx, v11 + by);
            }
        }
    }
}

__global__ __launch_bounds__(256, 2)
void gemm5(const __half* __restrict__ x1r, const __half* __restrict__ x2r,
           const __half* __restrict__ wt,
           __half* __restrict__ q1, __half* __restrict__ k, __half* __restrict__ v)
{
    const int z = blockIdx.z;
    const __half* A = (z < 3) ? x1r : x2r;
    const __half* W = wt + (size_t)z * WSZ;
    const size_t kvs  = (size_t)NKV * INNER;
    const size_t off2 = (size_t)N1 * INNER;
    __half* Cp; size_t cs, co; float sc;
    if (z == 0)      { Cp = q1; cs = (size_t)N1 * INNER; co = 0;    sc = SCALE_Q; }
    else if (z == 1) { Cp = k;  cs = kvs;                co = 0;    sc = 1.f; }
    else if (z == 2) { Cp = v;  cs = kvs;                co = 0;    sc = 1.f; }
    else if (z == 3) { Cp = k;  cs = kvs;                co = off2; sc = 1.f; }
    else             { Cp = v;  cs = kvs;                co = off2; sc = 1.f; }
    gemm_core(A, W, Cp, nullptr, D, INNER, cs, co, sc, true);
}

__global__ __launch_bounds__(256, 2)
void gemmO(const __half* __restrict__ ao, const __half* __restrict__ wt5,
           float* __restrict__ out, const float* __restrict__ bo)
{
    gemm_core(ao, wt5, out, bo, INNER, D, (size_t)N1 * D, 0, 1.f, false);
}

// ---------------------------------------------------------------------------
// Flash attention v10: split-KV x4, 4-stage ring, 1 barrier / 2 tiles,
// lazy max + MMA row sums + f16x2 packed exp (half the MUFU ops).
// ---------------------------------------------------------------------------
#define APH 72
#define KV_H   (64 * APH)           // halves per K (or V) tile
#define FBUF_H (2 * KV_H)           // halves per stage (K+V)

__global__ __launch_bounds__(256, 2)
void flash10(const __half* __restrict__ q, const __half* __restrict__ kc,
             const __half* __restrict__ vc,
             __half* __restrict__ aop, float2* __restrict__ ml)
{
    extern __shared__ __half fsm[];

    const int z  = blockIdx.z;
    const int b  = z >> 2;            // NSPLIT == 4
    const int sp = z & 3;
    const int h  = blockIdx.y;
    const int qt = blockIdx.x;
    const int tid  = threadIdx.x;
    const int w = tid >> 5, lane = tid & 31;
    const int g = lane >> 2, tg = lane & 3;
    const int m0 = 16 * w;

    const __half* qb = q  + ((size_t)b * N1 + (size_t)qt * 128) * INNER + h * DHEAD;
    const __half* kb = kc + ((size_t)b * NKV + (size_t)sp * KVS) * INNER + h * DHEAD;
    const __half* vb = vc + ((size_t)b * NKV + (size_t)sp * KVS) * INNER + h * DHEAD;

    const uint32_t smb = smem_u32(fsm);

    const int cr = tid >> 2;
    const int cc0 = (tid & 3) * 16;
    const uint32_t rowK = (uint32_t)(cr * APH + cc0) * 2;
    const uint32_t rowV = rowK + KV_H * 2;

    // --- preload KV tiles 0,1 into stages 0,1 ---
    #pragma unroll
    for (int s = 0; s < 2; s++) {
        const uint32_t sb = smb + (uint32_t)(s * FBUF_H) * 2;
        const __half* ks = kb + (size_t)s * 64 * INNER + (size_t)cr * INNER + cc0;
        const __half* vs = vb + (size_t)s * 64 * INNER + (size_t)cr * INNER + cc0;
        #pragma unroll
        for (int c = 0; c < 2; c++) {
            cpasync16(sb + rowK + 16 * c, ks + 8 * c);
            cpasync16(sb + rowV + 16 * c, vs + 8 * c);
        }
        CP_COMMIT();
    }

    // --- Q A-fragments from gmem ---
    uint32_t qaf[4][4];
    {
        const __half* q0 = qb + (size_t)(m0 + g) * INNER;
        const __half* q1r = q0 + 8 * INNER;
        #pragma unroll
        for (int s = 0; s < 4; s++) {
            qaf[s][0] = ldh2(q0  + 16 * s + 2 * tg);
            qaf[s][1] = ldh2(q1r + 16 * s + 2 * tg);
            qaf[s][2] = ldh2(q0  + 16 * s + 2 * tg + 8);
            qaf[s][3] = ldh2(q1r + 16 * s + 2 * tg + 8);
        }
    }

    float accO[8][4] = {};
    float mrun0 = 0.f, mrun1 = 0.f, lrun0 = 0.f, lrun1 = 0.f;

    const int sub = lane >> 3, rw = lane & 7;
    const int k_roff = (sub >> 1) * 8, k_koff = (sub & 1) * 8;
    const int vr = (sub & 1) * 8 + rw;
    const int vcb = (sub >> 1) * 8;

    const uint32_t bones[2] = { 0x3C003C00u, 0x3C003C00u };   // f16 ones B-frag

    const int NT = KVS / 64;     // 16
    for (int r = 0; r < NT / 2; r++) {
        __syncthreads();   // all warps done with tiles 2r-2, 2r-1 (stage reuse)

        const int jp0 = 2 * r + 2;
        if (jp0 < NT) {
            #pragma unroll
            for (int t = 0; t < 2; t++) {
                const int jp = jp0 + t;
                const uint32_t sb = smb + (uint32_t)((jp & 3) * FBUF_H) * 2;
                const __half* ks = kb + (size_t)jp * 64 * INNER + (size_t)cr * INNER + cc0;
                const __half* vs = vb + (size_t)jp * 64 * INNER + (size_t)cr * INNER + cc0;
                #pragma unroll
                for (int c = 0; c < 2; c++) {
                    cpasync16(sb + rowK + 16 * c, ks + 8 * c);
                    cpasync16(sb + rowV + 16 * c, vs + 8 * c);
                }
                CP_COMMIT();
            }
            CP_WAIT2();
        } else {
            CP_WAIT0();
        }

        #pragma unroll
        for (int t = 0; t < 2; t++) {
            const int j = 2 * r + t;
            const uint32_t ksb = smb + (uint32_t)((j & 3) * FBUF_H) * 2;
            const uint32_t vsb = ksb + KV_H * 2;

            // --- S = Q @ K^T ---
            float sacc[8][4] = {};
            #pragma unroll
            for (int ks = 0; ks < 4; ks++) {
                const int k0 = 16 * ks;
                #pragma unroll
                for (int np = 0; np < 4; np++) {
                    uint32_t b0, b1, b2, b3;
                    const uint32_t ka = ksb +
                        (uint32_t)((16 * np + k_roff + rw) * APH + k0 + k_koff) * 2;
                    ldmatrix_x4(b0, b1, b2, b3, ka);
                    uint32_t bf0[2] = { b0, b1 };
                    uint32_t bf1[2] = { b2, b3 };
                    mma_f16(sacc[2 * np],     qaf[ks], bf0);
                    mma_f16(sacc[2 * np + 1], qaf[ks], bf1);
                }
            }

            // --- tile 0: establish proper initial max before first exp ---
            if (j == 0) {
                float im0 = -1e30f, im1 = -1e30f;
                #pragma unroll
                for (int nt = 0; nt < 8; nt++) {
                    im0 = fmaxf(im0, fmaxf(sacc[nt][0], sacc[nt][1]));
                    im1 = fmaxf(im1, fmaxf(sacc[nt][2], sacc[nt][3]));
                }
                #pragma unroll
                for (int off = 1; off <= 2; off <<= 1) {
                    im0 = fmaxf(im0, __shfl_xor_sync(0xFFFFFFFFu, im0, off));
                    im1 = fmaxf(im1, __shfl_xor_sync(0xFFFFFFFFu, im1, off));
                }
                mrun0 = im0;
                mrun1 = im1;
            }

            // --- exp with (stale) running max, packed f16x2 ex2 ---
            uint32_t paf[4][4];
            #pragma unroll
            for (int ks = 0; ks < 4; ks++) {
                const int e0 = 2 * ks, e1 = 2 * ks + 1;
                paf[ks][0] = h2ex2(packh2(sacc[e0][0] - mrun0, sacc[e0][1] - mrun0));
                paf[ks][1] = h2ex2(packh2(sacc[e0][2] - mrun1, sacc[e0][3] - mrun1));
                paf[ks][2] = h2ex2(packh2(sacc[e1][0] - mrun0, sacc[e1][1] - mrun0));
                paf[ks][3] = h2ex2(packh2(sacc[e1][2] - mrun1, sacc[e1][3] - mrun1));
            }

            // --- trailing max reduce (off the exp critical path) ---
            float rm0 = -1e30f, rm1 = -1e30f;
            #pragma unroll
            for (int nt = 0; nt < 8; nt++) {
                rm0 = fmaxf(rm0, fmaxf(sacc[nt][0], sacc[nt][1]));
                rm1 = fmaxf(rm1, fmaxf(sacc[nt][2], sacc[nt][3]));
            }
            #pragma unroll
            for (int off = 1; off <= 2; off <<= 1) {
                rm0 = fmaxf(rm0, __shfl_xor_sync(0xFFFFFFFFu, rm0, off));
                rm1 = fmaxf(rm1, __shfl_xor_sync(0xFFFFFFFFu, rm1, off));
            }

            // --- row sums via MMA with ones ---
            float sumacc[4] = { 0.f, 0.f, 0.f, 0.f };
            #pragma unroll
            for (int ks = 0; ks < 4; ks++)
                mma_f16(sumacc, paf[ks], bones);

            // --- O += P @ V ---
            #pragma unroll
            for (int ks = 0; ks < 4; ks++) {
                #pragma unroll
                for (int dp = 0; dp < 4; dp++) {
                    uint32_t r0, r1, r2, r3;
                    const uint32_t addr = vsb +
                        (uint32_t)((16 * ks + vr) * APH + 16 * dp + vcb) * 2;
                    ldmatrix_x4_trans(r0, r1, r2, r3, addr);
                    uint32_t bf0[2] = { r0, r1 };
                    uint32_t bf1[2] = { r2, r3 };
                    mma_f16(accO[2 * dp],     paf[ks], bf0);
                    mma_f16(accO[2 * dp + 1], paf[ks], bf1);
                }
            }

            lrun0 += sumacc[0];
            lrun1 += sumacc[2];

            // --- deferred rescale (rare) ---
            const float mn0 = fmaxf(mrun0, rm0);
            const float mn1 = fmaxf(mrun1, rm1);
            const float al0 = exp2f(mrun0 - mn0);
            const float al1 = exp2f(mrun1 - mn1);
            if (!__all_sync(0xFFFFFFFFu, (al0 == 1.f) && (al1 == 1.f))) {
                #pragma unroll
                for (int nt = 0; nt < 8; nt++) {
                    accO[nt][0] *= al0; accO[nt][1] *= al0;
                    accO[nt][2] *= al1; accO[nt][3] *= al1;
                }
                lrun0 *= al0;
                lrun1 *= al1;
            }
            mrun0 = mn0;
            mrun1 = mn1;
        }
    }

    // --- write UNNORMALIZED partial O (f16) + (m,l) per row ---
    {
        const int qr0 = qt * 128 + m0 + g;
        __half* d0 = aop + (size_t)sp * PBUF
                   + ((size_t)b * N1 + qr0) * INNER + h * DHEAD;
        __half* d1 = d0 + 8 * INNER;
        #pragma unroll
        for (int nt = 0; nt < 8; nt++) {
            const int cc = 8 * nt + 2 * tg;
            *(uint32_t*)(d0 + cc) = packh2(accO[nt][0], accO[nt][1]);
            *(uint32_t*)(d1 + cc) = packh2(accO[nt][2], accO[nt][3]);
        }
        if (tg == 0) {
            float2* mlp = ml + (size_t)sp * MBUF
                        + ((size_t)b * HEADS + h) * N1;
            mlp[qr0]     = make_float2(mrun0, lrun0);
            mlp[qr0 + 8] = make_float2(mrun1, lrun1);
        }
    }
}

// ---------------------------------------------------------------------------
// Combine NSPLIT partials (unchanged).
// ---------------------------------------------------------------------------
__global__ __launch_bounds__(256)
void combine4(const __half* __restrict__ aop, const float2* __restrict__ ml,
              __half* __restrict__ ao)
{
    const int bid = blockIdx.x;
    const int b   = bid >> 11;           // N1 == 2048
    const int row = bid & 2047;
    const int t   = threadIdx.x;
    const int h   = t >> 5;
    const int d   = (t & 31) * 2;

    const size_t mlIdx = ((size_t)b * HEADS + h) * N1 + row;
    float2 m0 = ml[0 * MBUF + mlIdx];
    float2 m1 = ml[1 * MBUF + mlIdx];
    float2 m2 = ml[2 * MBUF + mlIdx];
    float2 m3 = ml[3 * MBUF + mlIdx];

    const float mm = fmaxf(fmaxf(m0.x, m1.x), fmaxf(m2.x, m3.x));
    const float w0 = exp2f(m0.x - mm);
    const float w1 = exp2f(m1.x - mm);
    const float w2 = exp2f(m2.x - mm);
    const float w3 = exp2f(m3.x - mm);
    const float inv = 1.0f / (w0 * m0.y + w1 * m1.y + w2 * m2.y + w3 * m3.y);

    const size_t ofs = ((size_t)b * N1 + row) * INNER + h * DHEAD + d;
    const __half2 o0 = *(const __half2*)(aop + 0 * PBUF + ofs);
    const __half2 o1 = *(const __half2*)(aop + 1 * PBUF + ofs);
    const __half2 o2 = *(const __half2*)(aop + 2 * PBUF + ofs);
    const __half2 o3 = *(const __half2*)(aop + 3 * PBUF + ofs);

    const float2 f0 = __half22float2(o0);
    const float2 f1 = __half22float2(o1);
    const float2 f2 = __half22float2(o2);
    const float2 f3 = __half22float2(o3);

    const float ox = (w0 * f0.x + w1 * f1.x + w2 * f2.x + w3 * f3.x) * inv;
    const float oy = (w0 * f0.y + w1 * f1.y + w2 * f2.y + w3 * f3.y) * inv;
    *(uint32_t*)(ao + ofs) = packh2(ox, oy);
}

// ---------------------------------------------------------------------------
// Launch
// ---------------------------------------------------------------------------
extern "C" void kernel_launch(void* const* d_in, const int* in_sizes, int n_in,
                              void* d_out, int out_size)
{
    (void)in_sizes; (void)n_in; (void)out_size;

    const float* x1  = (const float*)d_in[0];
    const float* x2  = (const float*)d_in[1];
    const float* Wq1 = (const float*)d_in[2];
    const float* Wk1 = (const float*)d_in[3];
    const float* Wv1 = (const float*)d_in[4];
    const float* Wk2 = (const float*)d_in[5];
    const float* Wv2 = (const float*)d_in[6];
    const float* Wo  = (const float*)d_in[7];
    const float* bo  = (const float*)d_in[8];
    float* out = (float*)d_out;

    __half *q1, *kbuf, *vbuf, *aobuf, *wt, *xr, *aop;
    float2* mlb;
    cudaGetSymbolAddress((void**)&q1,    g_q1);
    cudaGetSymbolAddress((void**)&kbuf,  g_k);
    cudaGetSymbolAddress((void**)&vbuf,  g_v);
    cudaGetSymbolAddress((void**)&aobuf, g_ao);
    cudaGetSymbolAddress((void**)&wt,    g_wt);
    cudaGetSymbolAddress((void**)&xr,    g_xr);
    cudaGetSymbolAddress((void**)&aop,   g_aop);
    cudaGetSymbolAddress((void**)&mlb,   g_ml);

    const int gemm_smem  = 2 * GSTG_H * (int)sizeof(__half);  // 37888
    const int flash_smem = 4 * FBUF_H * (int)sizeof(__half);  // 73728
    cudaFuncSetAttribute(gemm5,   cudaFuncAttributeMaxDynamicSharedMemorySize, gemm_smem);
    cudaFuncSetAttribute(gemmO,   cudaFuncAttributeMaxDynamicSharedMemorySize, gemm_smem);
    cudaFuncSetAttribute(flash10, cudaFuncAttributeMaxDynamicSharedMemorySize, flash_smem);

    conv_w<<<dim3(128, 1, 6), 256>>>(Wq1, Wk1, Wv1, Wk2, Wv2, Wo, wt);
    conv_x<<<4096, 256>>>(x1, x2, xr);

    gemm5<<<dim3(INNER / 128, MTOT / 128, 5), 256, gemm_smem>>>(
        xr, xr + (size_t)MTOT * D, wt, q1, kbuf, vbuf);

    flash10<<<dim3(N1 / 128, HEADS, B * NSPLIT), 256, flash_smem>>>(
        q1, kbuf, vbuf, aop, mlb);

    combine4<<<B * N1, 256>>>(aop, mlb, aobuf);

    gemmO<<<dim3(D / 128, MTOT / 128, 1), 256, gemm_smem>>>(aobuf, wt + 5 * WSZ, out, bo);
}